// round 12
// baseline (speedup 1.0000x reference)
#include <cuda_runtime.h>
#include <cuda_bf16.h>
#include <cstdint>
#include <math.h>

// Block_36455682408804: transformer block  B=16 T=1024 D=128 H=8 HS=16 FF=512
#define BT_TOTAL 16384
#define DMODEL   128
#define FFDIM    512
#define NQKV     384

// ---------------------------------------------------------------------------
// device-global scratch (allocation-free, graph-capturable)
// ---------------------------------------------------------------------------
__device__ float g_x1 [BT_TOTAL * DMODEL];                // fp32 residual for MLP2
__device__ float g_bqkv[NQKV];
__device__ __nv_bfloat16 g_xh [BT_TOTAL * DMODEL], g_xl [BT_TOTAL * DMODEL];
__device__ __nv_bfloat16 g_qh [128 * 1024 * 16],   g_ql [128 * 1024 * 16];   // [bh][t][16], pre-scaled 0.25*log2e
__device__ __nv_bfloat16 g_kh [128 * 1024 * 16],   g_kl [128 * 1024 * 16];   // [bh][t][16]
__device__ __nv_bfloat16 g_vh [128 * 1024 * 16],   g_vl [128 * 1024 * 16];   // [bh][t][16]
__device__ __nv_bfloat16 g_ath[BT_TOTAL * DMODEL], g_atl[BT_TOTAL * DMODEL];
__device__ __nv_bfloat16 g_x1h[BT_TOTAL * DMODEL], g_x1l[BT_TOTAL * DMODEL];
__device__ __nv_bfloat16 g_hih[BT_TOTAL * FFDIM],  g_hil[BT_TOTAL * FFDIM];
__device__ __nv_bfloat16 g_wqkv_h[NQKV * DMODEL],  g_wqkv_l[NQKV * DMODEL];
__device__ __nv_bfloat16 g_wp_h[DMODEL * DMODEL],  g_wp_l[DMODEL * DMODEL];
__device__ __nv_bfloat16 g_w1_h[FFDIM * DMODEL],   g_w1_l[FFDIM * DMODEL];
__device__ __nv_bfloat16 g_w2_h[DMODEL * FFDIM],   g_w2_l[DMODEL * FFDIM];

// ---------------------------------------------------------------------------
// helpers
// ---------------------------------------------------------------------------
__device__ __forceinline__ void split_bf(float v, __nv_bfloat16& h, __nv_bfloat16& l) {
    h = __float2bfloat16(v);
    l = __float2bfloat16(v - __bfloat162float(h));
}
__device__ __forceinline__ void split2(float x, float y, uint32_t& h, uint32_t& l) {
    asm("cvt.rn.bf16x2.f32 %0, %1, %2;" : "=r"(h) : "f"(y), "f"(x));
    float xh = __uint_as_float(h << 16);
    float yh = __uint_as_float(h & 0xffff0000u);
    float xl = x - xh, yl = y - yh;
    asm("cvt.rn.bf16x2.f32 %0, %1, %2;" : "=r"(l) : "f"(yl), "f"(xl));
}
__device__ __forceinline__ float ex2f(float x) {
    float r; asm("ex2.approx.f32 %0, %1;" : "=f"(r) : "f"(x)); return r;
}
__device__ __forceinline__ uint32_t smem_u32(const void* p) {
    uint32_t a;
    asm("{ .reg .u64 t; cvta.to.shared.u64 t, %1; cvt.u32.u64 %0, t; }" : "=r"(a) : "l"(p));
    return a;
}
__device__ __forceinline__ void ldsm4(uint32_t addr, uint32_t* r) {
    asm volatile("ldmatrix.sync.aligned.m8n8.x4.shared.b16 {%0,%1,%2,%3}, [%4];"
                 : "=r"(r[0]), "=r"(r[1]), "=r"(r[2]), "=r"(r[3]) : "r"(addr));
}
__device__ __forceinline__ void ldsm4t(uint32_t addr, uint32_t* r) {
    asm volatile("ldmatrix.sync.aligned.m8n8.x4.trans.shared.b16 {%0,%1,%2,%3}, [%4];"
                 : "=r"(r[0]), "=r"(r[1]), "=r"(r[2]), "=r"(r[3]) : "r"(addr));
}
__device__ __forceinline__ void mma_bf16(float* d, const uint32_t* a, uint32_t b0, uint32_t b1) {
    asm volatile("mma.sync.aligned.m16n8k16.row.col.f32.bf16.bf16.f32 "
                 "{%0,%1,%2,%3}, {%4,%5,%6,%7}, {%8,%9}, {%0,%1,%2,%3};"
                 : "+f"(d[0]), "+f"(d[1]), "+f"(d[2]), "+f"(d[3])
                 : "r"(a[0]), "r"(a[1]), "r"(a[2]), "r"(a[3]), "r"(b0), "r"(b1));
}
__device__ __forceinline__ void cp16(uint32_t saddr, const void* gptr) {
    asm volatile("cp.async.cg.shared.global [%0], [%1], 16;" :: "r"(saddr), "l"(gptr));
}
__device__ __forceinline__ void cp_commit() { asm volatile("cp.async.commit_group;"); }
__device__ __forceinline__ void cp_wait0() { asm volatile("cp.async.wait_group 0;"); }
__device__ __forceinline__ void cp_wait1() { asm volatile("cp.async.wait_group 1;"); }
__device__ __forceinline__ float gelu_f(float v) {
    return 0.5f * v * (1.f + erff(v * 0.7071067811865475f));
}

// ---------------------------------------------------------------------------
// pack weights: transpose to [N,K], split bf16 hi/lo
// ---------------------------------------------------------------------------
__global__ void pack_kernel(const float* __restrict__ Wq, const float* __restrict__ bq,
                            const float* __restrict__ Wk, const float* __restrict__ bk,
                            const float* __restrict__ Wv, const float* __restrict__ bv,
                            const float* __restrict__ Wp, const float* __restrict__ W1,
                            const float* __restrict__ W2)
{
    int i0 = blockIdx.x * blockDim.x + threadIdx.x;
    int stride = gridDim.x * blockDim.x;
    for (int i = i0; i < NQKV * DMODEL; i += stride) {
        int n = i >> 7, k = i & 127;
        float v;
        if (n < 128)      v = Wq[((n >> 4) << 11) + k * 16 + (n & 15)];
        else if (n < 256) { int m = n - 128; v = Wk[((m >> 4) << 11) + k * 16 + (m & 15)]; }
        else              { int m = n - 256; v = Wv[((m >> 4) << 11) + k * 16 + (m & 15)]; }
        split_bf(v, g_wqkv_h[i], g_wqkv_l[i]);
    }
    for (int i = i0; i < DMODEL * DMODEL; i += stride) {
        int n = i >> 7, k = i & 127;
        split_bf(Wp[k * 128 + n], g_wp_h[i], g_wp_l[i]);
    }
    for (int i = i0; i < FFDIM * DMODEL; i += stride) {
        int n = i >> 7, k = i & 127;
        split_bf(W1[k * 512 + n], g_w1_h[i], g_w1_l[i]);
    }
    for (int i = i0; i < DMODEL * FFDIM; i += stride) {
        int n = i >> 9, k = i & 511;
        split_bf(W2[k * 128 + n], g_w2_h[i], g_w2_l[i]);
    }
    for (int i = i0; i < NQKV; i += stride)
        g_bqkv[i] = (i < 128) ? bq[i] : (i < 256 ? bk[i - 128] : bv[i - 256]);
}

// split activations x -> xh, xl
__global__ void split_x_kernel(const float* __restrict__ X,
                               __nv_bfloat16* __restrict__ Xh, __nv_bfloat16* __restrict__ Xl)
{
    int i = blockIdx.x * blockDim.x + threadIdx.x;
    float4 v = ((const float4*)X)[i];
    uint32_t h0, l0, h1, l1;
    split2(v.x, v.y, h0, l0); split2(v.z, v.w, h1, l1);
    ((uint2*)Xh)[i] = make_uint2(h0, h1);
    ((uint2*)Xl)[i] = make_uint2(l0, l1);
}

// ---------------------------------------------------------------------------
// HMMA GEMM, all-bf16 inputs, cp.async 2-stage pipeline, 256 threads.
// CTA tile 64x128 (M x N), 8 warps (2m x 4n), warp tile 32x32, K chunk 64.
// flags: 1=gelu, 2=LN(+resid), 4=write fp32, 8=write bf16 hi/lo, 16=QKV layout
// ---------------------------------------------------------------------------
#define FL_GELU 1
#define FL_LN   2
#define FL_F32  4
#define FL_BF   8
#define FL_QKV  16

#define SM_AH 0
#define SM_AL 8192
#define SM_BH 16384
#define SM_BL 32768
#define SM_STAGE 49152
#define SM_CS 0
#define SM_BIAS 98304
#define SM_G    98816
#define SM_BE   99328
#define SM_TOTAL 99840

__global__ __launch_bounds__(256, 2)
void gemm_mma(const __nv_bfloat16* __restrict__ Ah_, const __nv_bfloat16* __restrict__ Al_,
              int K,
              const __nv_bfloat16* __restrict__ Bh_, const __nv_bfloat16* __restrict__ Bl_,
              const float* __restrict__ bias, const float* __restrict__ resid,
              const float* __restrict__ gamma, const float* __restrict__ beta,
              float* __restrict__ Cf, __nv_bfloat16* __restrict__ Cbh, __nv_bfloat16* __restrict__ Cbl,
              int ldc, int flags)
{
    extern __shared__ unsigned char smraw[];
    const uint32_t smem_base = smem_u32(smraw);
    float* sBias = (float*)(smraw + SM_BIAS);
    float* sG    = (float*)(smraw + SM_G);
    float* sBe   = (float*)(smraw + SM_BE);
    float* Cs    = (float*)(smraw + SM_CS);

    const int tid = threadIdx.x;
    const int wid = tid >> 5, lane = tid & 31;
    const int m0 = blockIdx.x * 64, n0 = blockIdx.y * 128;
    const int wm = (wid & 1) * 32, wn = (wid >> 1) * 32;

    if (tid < 128) {
        sBias[tid] = bias[n0 + tid];
        if (flags & FL_LN) { sG[tid] = gamma[tid]; sBe[tid] = beta[tid]; }
    }

    const int q = lane >> 3, rin = lane & 7;
    const int rowA0 = wm + (q & 1) * 8 + rin;
    const int kqoff = (q >> 1) * 16;

    const int ar = tid >> 2, aq = tid & 3;
    const int br = tid >> 1, bq2 = tid & 1;
    const uint32_t aswz = (uint32_t)(ar & 7) << 4;
    const uint32_t bswz = (uint32_t)(br & 7) << 4;

    float acc[2][4][4];
    #pragma unroll
    for (int i = 0; i < 2; ++i)
        #pragma unroll
        for (int j = 0; j < 4; ++j)
            #pragma unroll
            for (int e = 0; e < 4; ++e) acc[i][j][e] = 0.f;

    const int nchunks = K >> 6;
    const size_t arow = (size_t)(m0 + ar) * K;
    const size_t brow = (size_t)(n0 + br) * K;

    {
        #pragma unroll
        for (int g = 0; g < 2; ++g) {
            int slot = aq * 2 + g;
            uint32_t off = (uint32_t)ar * 128 + (((uint32_t)slot * 16) ^ aswz);
            cp16(smem_base + SM_AH + off, Ah_ + arow + slot * 8);
            cp16(smem_base + SM_AL + off, Al_ + arow + slot * 8);
        }
        #pragma unroll
        for (int g = 0; g < 4; ++g) {
            int slot = bq2 * 4 + g;
            uint32_t off = (uint32_t)br * 128 + (((uint32_t)slot * 16) ^ bswz);
            cp16(smem_base + SM_BH + off, Bh_ + brow + slot * 8);
            cp16(smem_base + SM_BL + off, Bl_ + brow + slot * 8);
        }
        cp_commit();
    }

    for (int c = 0; c < nchunks; ++c) {
        if (c + 1 < nchunks) {
            const int kc = (c + 1) << 6;
            const uint32_t sb = smem_base + ((c + 1) & 1) * SM_STAGE;
            #pragma unroll
            for (int g = 0; g < 2; ++g) {
                int slot = aq * 2 + g;
                uint32_t off = (uint32_t)ar * 128 + (((uint32_t)slot * 16) ^ aswz);
                cp16(sb + SM_AH + off, Ah_ + arow + kc + slot * 8);
                cp16(sb + SM_AL + off, Al_ + arow + kc + slot * 8);
            }
            #pragma unroll
            for (int g = 0; g < 4; ++g) {
                int slot = bq2 * 4 + g;
                uint32_t off = (uint32_t)br * 128 + (((uint32_t)slot * 16) ^ bswz);
                cp16(sb + SM_BH + off, Bh_ + brow + kc + slot * 8);
                cp16(sb + SM_BL + off, Bl_ + brow + kc + slot * 8);
            }
            cp_commit();
            cp_wait1();
        } else {
            cp_wait0();
        }
        __syncthreads();
        const uint32_t sb = smem_base + (c & 1) * SM_STAGE;
        #pragma unroll
        for (int ks = 0; ks < 4; ++ks) {
            const uint32_t kb = (uint32_t)(ks * 32 + kqoff);
            uint32_t ah[2][4], al[2][4], bh[4][2], bl[4][2];
            #pragma unroll
            for (int i = 0; i < 2; ++i) {
                uint32_t row = (uint32_t)(rowA0 + i * 16);
                uint32_t off = row * 128 + (kb ^ ((row & 7) << 4));
                ldsm4(sb + SM_AH + off, ah[i]);
                ldsm4(sb + SM_AL + off, al[i]);
            }
            #pragma unroll
            for (int j2 = 0; j2 < 2; ++j2) {
                uint32_t row = (uint32_t)(wn + j2 * 16 + (q & 1) * 8 + rin);
                uint32_t off = row * 128 + (kb ^ ((row & 7) << 4));
                uint32_t r4v[4];
                ldsm4(sb + SM_BH + off, r4v);
                bh[2*j2][0] = r4v[0]; bh[2*j2][1] = r4v[2];
                bh[2*j2+1][0] = r4v[1]; bh[2*j2+1][1] = r4v[3];
                ldsm4(sb + SM_BL + off, r4v);
                bl[2*j2][0] = r4v[0]; bl[2*j2][1] = r4v[2];
                bl[2*j2+1][0] = r4v[1]; bl[2*j2+1][1] = r4v[3];
            }
            #pragma unroll
            for (int i = 0; i < 2; ++i)
                #pragma unroll
                for (int j = 0; j < 4; ++j) {
                    mma_bf16(acc[i][j], ah[i], bh[j][0], bh[j][1]);
                    mma_bf16(acc[i][j], ah[i], bl[j][0], bl[j][1]);
                    mma_bf16(acc[i][j], al[i], bh[j][0], bh[j][1]);
                }
        }
        __syncthreads();
    }

    if (flags & FL_QKV) {
        __nv_bfloat16 *dsth, *dstl;
        float scale;
        if (n0 == 0)        { dsth = g_qh; dstl = g_ql; scale = 0.36067376022224085f; }  // 0.25*log2(e)
        else if (n0 == 128) { dsth = g_kh; dstl = g_kl; scale = 1.f; }
        else                { dsth = g_vh; dstl = g_vl; scale = 1.f; }
        #pragma unroll
        for (int i = 0; i < 2; ++i)
            #pragma unroll
            for (int j = 0; j < 4; ++j) {
                int cp = wn + j * 8 + (lane & 3) * 2;
                float b0 = sBias[cp], b1 = sBias[cp + 1];
                int hh8 = (cp >> 4) & 7, e = cp & 15;
                #pragma unroll
                for (int rr = 0; rr < 2; ++rr) {
                    int r = m0 + wm + i * 16 + (lane >> 2) + rr * 8;
                    float v0 = (acc[i][j][rr * 2 + 0] + b0) * scale;
                    float v1 = (acc[i][j][rr * 2 + 1] + b1) * scale;
                    int bb = r >> 10, t = r & 1023;
                    int bh128 = bb * 8 + hh8;
                    uint32_t hh, ll;
                    split2(v0, v1, hh, ll);
                    size_t idx = ((size_t)bh128 * 1024 + t) * 16 + e;
                    *(uint32_t*)(dsth + idx) = hh;
                    *(uint32_t*)(dstl + idx) = ll;
                }
            }
    } else if (!(flags & FL_LN)) {
        #pragma unroll
        for (int i = 0; i < 2; ++i)
            #pragma unroll
            for (int j = 0; j < 4; ++j) {
                int cp = wn + j * 8 + (lane & 3) * 2;
                float b0 = sBias[cp], b1 = sBias[cp + 1];
                int r0 = m0 + wm + i * 16 + (lane >> 2);
                float v0 = acc[i][j][0] + b0, v1 = acc[i][j][1] + b1;
                float v2 = acc[i][j][2] + b0, v3 = acc[i][j][3] + b1;
                if (flags & FL_GELU) { v0 = gelu_f(v0); v1 = gelu_f(v1); v2 = gelu_f(v2); v3 = gelu_f(v3); }
                if (flags & FL_F32) {
                    *(float2*)(Cf + (size_t)r0 * ldc + n0 + cp)       = make_float2(v0, v1);
                    *(float2*)(Cf + (size_t)(r0 + 8) * ldc + n0 + cp) = make_float2(v2, v3);
                }
                if (flags & FL_BF) {
                    uint32_t hh, ll;
                    split2(v0, v1, hh, ll);
                    *(uint32_t*)(Cbh + (size_t)r0 * ldc + n0 + cp) = hh;
                    *(uint32_t*)(Cbl + (size_t)r0 * ldc + n0 + cp) = ll;
                    split2(v2, v3, hh, ll);
                    *(uint32_t*)(Cbh + (size_t)(r0 + 8) * ldc + n0 + cp) = hh;
                    *(uint32_t*)(Cbl + (size_t)(r0 + 8) * ldc + n0 + cp) = ll;
                }
            }
    } else {
        #pragma unroll
        for (int i = 0; i < 2; ++i)
            #pragma unroll
            for (int j = 0; j < 4; ++j) {
                int cp = wn + j * 8 + (lane & 3) * 2;
                float b0 = sBias[cp], b1 = sBias[cp + 1];
                int r0 = wm + i * 16 + (lane >> 2);
                Cs[r0 * 132 + cp]           = acc[i][j][0] + b0;
                Cs[r0 * 132 + cp + 1]       = acc[i][j][1] + b1;
                Cs[(r0 + 8) * 132 + cp]     = acc[i][j][2] + b0;
                Cs[(r0 + 8) * 132 + cp + 1] = acc[i][j][3] + b1;
            }
        __syncthreads();
        for (int rr = 0; rr < 8; ++rr) {
            int row = wid * 8 + rr;
            const float* cr = Cs + row * 132 + lane * 4;
            float2 p0 = *(const float2*)(cr);
            float2 p1 = *(const float2*)(cr + 2);
            const float4 rv = *(const float4*)(resid + (size_t)(m0 + row) * 128 + lane * 4);
            float v0 = p0.x + rv.x, v1 = p0.y + rv.y, v2 = p1.x + rv.z, v3 = p1.y + rv.w;
            float s  = v0 + v1 + v2 + v3;
            float sq2 = v0 * v0 + v1 * v1 + v2 * v2 + v3 * v3;
            #pragma unroll
            for (int off = 16; off > 0; off >>= 1) {
                s   += __shfl_xor_sync(0xffffffffu, s,   off);
                sq2 += __shfl_xor_sync(0xffffffffu, sq2, off);
            }
            float mean = s * (1.f / 128.f);
            float var  = sq2 * (1.f / 128.f) - mean * mean;
            float is   = rsqrtf(var + 1e-5f);
            int cb = lane * 4;
            float o0 = (v0 - mean) * is * sG[cb]     + sBe[cb];
            float o1 = (v1 - mean) * is * sG[cb + 1] + sBe[cb + 1];
            float o2 = (v2 - mean) * is * sG[cb + 2] + sBe[cb + 2];
            float o3 = (v3 - mean) * is * sG[cb + 3] + sBe[cb + 3];
            size_t base = (size_t)(m0 + row) * 128 + cb;
            if (flags & FL_F32)
                *(float4*)(Cf + base) = make_float4(o0, o1, o2, o3);
            if (flags & FL_BF) {
                uint32_t hh, ll;
                split2(o0, o1, hh, ll);
                *(uint32_t*)(Cbh + base) = hh; *(uint32_t*)(Cbl + base) = ll;
                split2(o2, o3, hh, ll);
                *(uint32_t*)(Cbh + base + 2) = hh; *(uint32_t*)(Cbl + base + 2) = ll;
            }
        }
    }
}

// ---------------------------------------------------------------------------
// Flash-style causal attention via HMMA, DIAGONAL-BALANCED, 8 warps/CTA,
// cp.async double-buffered K/V staging. ex2-domain softmax (Q pre-scaled).
// K fragments via ldmatrix (like V) — no scalar LDS in the mainloop.
// ---------------------------------------------------------------------------
struct TileAcc {
    float o[2][4];
    float lsum[2];
};

__device__ __forceinline__ void attn_step(
    const uint32_t* aqh, const uint32_t* aql,
    const uint32_t* kfh, const uint32_t* kfl,     // K fragments (ldsm4: [jj0_b0, jj1_b0, jj0_b1, jj1_b1])
    int kbase, int W, int r4, int c2,
    const uint32_t* vbh, const uint32_t* vbl,
    TileAcc& T)
{
    float s[2][4];
    #pragma unroll
    for (int jj = 0; jj < 2; ++jj)
        #pragma unroll
        for (int e = 0; e < 4; ++e) s[jj][e] = 0.f;
    #pragma unroll
    for (int jj = 0; jj < 2; ++jj) {
        uint32_t kb0 = kfh[jj], kb1 = kfh[2 + jj];
        uint32_t kl0 = kfl[jj], kl1 = kfl[2 + jj];
        mma_bf16(s[jj], aqh, kb0, kb1);
        mma_bf16(s[jj], aqh, kl0, kl1);
        mma_bf16(s[jj], aql, kb0, kb1);
    }
    uint32_t pah[4], pal[4];
    const bool full = (kbase + 15 <= W);
    const int t0 = W + r4, t1 = t0 + 8;
    #pragma unroll
    for (int jj = 0; jj < 2; ++jj) {
        int ub = kbase + jj * 8 + c2;
        float p0 = ex2f(s[jj][0]);
        float p1 = ex2f(s[jj][1]);
        float p2 = ex2f(s[jj][2]);
        float p3 = ex2f(s[jj][3]);
        if (!full) {
            if (ub > t0)     p0 = 0.f;
            if (ub + 1 > t0) p1 = 0.f;
            if (ub > t1)     p2 = 0.f;
            if (ub + 1 > t1) p3 = 0.f;
        }
        T.lsum[0] += p0 + p1;
        T.lsum[1] += p2 + p3;
        split2(p0, p1, pah[jj * 2 + 0], pal[jj * 2 + 0]);
        split2(p2, p3, pah[jj * 2 + 1], pal[jj * 2 + 1]);
    }
    #pragma unroll
    for (int nt = 0; nt < 2; ++nt) {
        mma_bf16(T.o[nt], pah, vbh[nt * 2], vbh[nt * 2 + 1]);
        mma_bf16(T.o[nt], pah, vbl[nt * 2], vbl[nt * 2 + 1]);
        mma_bf16(T.o[nt], pal, vbh[nt * 2], vbh[nt * 2 + 1]);
    }
}

__global__ __launch_bounds__(256)
void attn_mma(const __nv_bfloat16* __restrict__ Qh, const __nv_bfloat16* __restrict__ Ql,
              const __nv_bfloat16* __restrict__ Kh, const __nv_bfloat16* __restrict__ Kl,
              const __nv_bfloat16* __restrict__ Vh, const __nv_bfloat16* __restrict__ Vl,
              __nv_bfloat16* __restrict__ Oh, __nv_bfloat16* __restrict__ Ol)
{
    __shared__ __align__(16) __nv_bfloat16 sKh[2][128 * 24], sKl[2][128 * 24];
    __shared__ __align__(16) __nv_bfloat16 sVh[2][128 * 24], sVl[2][128 * 24];

    const int pa = blockIdx.x;
    const int bh = blockIdx.y;
    const int a = pa, bqt = 15 - pa;
    const int tid = threadIdx.x;
    const int w = tid >> 5, lane = tid & 31;
    const int wg = w >> 2, wi = w & 3;
    const int myqt = wg ? bqt : a;
    const int W = myqt * 64 + wi * 16;
    const int r4 = lane >> 2, c2 = (lane & 3) * 2;
    const uint32_t skh0 = smem_u32(sKh[0]), skl0 = smem_u32(sKl[0]);
    const uint32_t skh1 = smem_u32(sKh[1]), skl1 = smem_u32(sKl[1]);
    const uint32_t svh0 = smem_u32(sVh[0]), svl0 = smem_u32(sVl[0]);
    const uint32_t svh1 = smem_u32(sVh[1]), svl1 = smem_u32(sVl[1]);

    const int mi = lane >> 3, li = lane & 7;
    const uint32_t vfrag_off = (uint32_t)(((li + (mi & 1) * 8) * 24 + (mi >> 1) * 8) * 2);
    // K fragment (non-trans ldsm): row = (mi&1)*8 + li within 16-key group, byte col = (mi>>1)*16
    const uint32_t kfrag_off = (uint32_t)(((mi & 1) * 8 + li) * 48 + (mi >> 1) * 16);

    if (tid < 128) {
        int qrow = (tid < 64) ? (a * 64 + tid) : (bqt * 64 + tid - 64);
        const __nv_bfloat16* srcH = Qh + ((size_t)bh * 1024 + qrow) * 16;
        const __nv_bfloat16* srcL = Ql + ((size_t)bh * 1024 + qrow) * 16;
        *(uint4*)&sKh[0][tid * 24]     = ((const uint4*)srcH)[0];
        *(uint4*)&sKh[0][tid * 24 + 8] = ((const uint4*)srcH)[1];
        *(uint4*)&sKl[0][tid * 24]     = ((const uint4*)srcL)[0];
        *(uint4*)&sKl[0][tid * 24 + 8] = ((const uint4*)srcL)[1];
    }
    __syncthreads();

    uint32_t aqh[4], aql[4];
    {
        uint32_t row = (uint32_t)(wg * 64 + wi * 16 + (mi & 1) * 8 + li);
        uint32_t boff = row * 48 + (uint32_t)(mi >> 1) * 16;
        ldsm4(skh0 + boff, aqh);
        ldsm4(skl0 + boff, aql);
    }
    __syncthreads();

    TileAcc T;
    #pragma unroll
    for (int nt = 0; nt < 2; ++nt)
        #pragma unroll
        for (int e = 0; e < 4; ++e) T.o[nt][e] = 0.f;
    T.lsum[0] = T.lsum[1] = 0.f;

    const int strow = tid >> 1, sthalf = tid & 1;
    const uint32_t stoff = (uint32_t)strow * 48 + (uint32_t)sthalf * 16;
    const size_t stg_base = ((size_t)bh * 1024 + strow) * 16 + sthalf * 8;

    const int ntiles = (bqt + 2) >> 1;
    {
        const size_t goff = stg_base;
        cp16(skh0 + stoff, Kh + goff);
        cp16(skl0 + stoff, Kl + goff);
        cp16(svh0 + stoff, Vh + goff);
        cp16(svl0 + stoff, Vl + goff);
        cp_commit();
    }

    for (int tile = 0; tile < ntiles; ++tile) {
        if (tile + 1 < ntiles) {
            const size_t goff = stg_base + (size_t)((tile + 1) << 7) * 16;
            const uint32_t kh = ((tile + 1) & 1) ? skh1 : skh0;
            const uint32_t kl = ((tile + 1) & 1) ? skl1 : skl0;
            const uint32_t vh = ((tile + 1) & 1) ? svh1 : svh0;
            const uint32_t vl = ((tile + 1) & 1) ? svl1 : svl0;
            cp16(kh + stoff, Kh + goff);
            cp16(kl + stoff, Kl + goff);
            cp16(vh + stoff, Vh + goff);
            cp16(vl + stoff, Vl + goff);
            cp_commit();
            cp_wait1();
        } else {
            cp_wait0();
        }
        __syncthreads();
        const int bi = tile & 1;
        const uint32_t ckh = bi ? skh1 : skh0;
        const uint32_t ckl = bi ? skl1 : skl0;
        const uint32_t cvh = bi ? svh1 : svh0;
        const uint32_t cvl = bi ? svl1 : svl0;
        const int u0 = tile << 7;

        if (u0 <= W + 15) {
            #pragma unroll
            for (int kk = 0; kk < 8; ++kk) {
                const int kbase = u0 + kk * 16;
                if (kbase > W + 15) break;
                uint32_t vbh[4], vbl[4], kfh[4], kfl[4];
                uint32_t tileoff = (uint32_t)(kk * 16 * 48);
                ldsm4t(cvh + vfrag_off + tileoff, vbh);
                ldsm4t(cvl + vfrag_off + tileoff, vbl);
                ldsm4(ckh + kfrag_off + tileoff, kfh);
                ldsm4(ckl + kfrag_off + tileoff, kfl);
                attn_step(aqh, aql, kfh, kfl, kbase, W, r4, c2, vbh, vbl, T);
            }
        }
        __syncthreads();
    }

    const int b = bh >> 3, h = bh & 7;
    const int bT = b << 10;
    {
        float l0 = T.lsum[0], l1 = T.lsum[1];
        l0 += __shfl_xor_sync(0xffffffffu, l0, 1);
        l0 += __shfl_xor_sync(0xffffffffu, l0, 2);
        l1 += __shfl_xor_sync(0xffffffffu, l1, 1);
        l1 += __shfl_xor_sync(0xffffffffu, l1, 2);
        float i0 = 1.f / l0, i1 = 1.f / l1;
        int row0 = bT + W + r4;
        #pragma unroll
        for (int nt = 0; nt < 2; ++nt) {
            int col = (h << 4) + nt * 8 + c2;
            uint32_t hh, ll;
            split2(T.o[nt][0] * i0, T.o[nt][1] * i0, hh, ll);
            *(uint32_t*)(Oh + (size_t)row0 * 128 + col) = hh;
            *(uint32_t*)(Ol + (size_t)row0 * 128 + col) = ll;
            split2(T.o[nt][2] * i1, T.o[nt][3] * i1, hh, ll);
            *(uint32_t*)(Oh + (size_t)(row0 + 8) * 128 + col) = hh;
            *(uint32_t*)(Ol + (size_t)(row0 + 8) * 128 + col) = ll;
        }
    }
}

// ---------------------------------------------------------------------------
extern "C" void kernel_launch(void* const* d_in, const int* in_sizes, int n_in,
                              void* d_out, int out_size)
{
    const float* x   = (const float*)d_in[0];
    const float* Wq  = (const float*)d_in[1];
    const float* bq  = (const float*)d_in[2];
    const float* Wk  = (const float*)d_in[3];
    const float* bk  = (const float*)d_in[4];
    const float* Wv  = (const float*)d_in[5];
    const float* bv  = (const float*)d_in[6];
    const float* Wp  = (const float*)d_in[7];
    const float* bp  = (const float*)d_in[8];
    const float* W1  = (const float*)d_in[9];
    const float* b1  = (const float*)d_in[10];
    const float* W2  = (const float*)d_in[11];
    const float* b2  = (const float*)d_in[12];
    const float* g1  = (const float*)d_in[13];
    const float* be1 = (const float*)d_in[14];
    const float* g2  = (const float*)d_in[15];
    const float* be2 = (const float*)d_in[16];
    float* out = (float*)d_out;

    float *p_x1, *p_bqkv;
    __nv_bfloat16 *p_xh, *p_xl, *p_qh, *p_ql, *p_kh, *p_kl, *p_vh, *p_vl;
    __nv_bfloat16 *p_ath, *p_atl, *p_x1h, *p_x1l, *p_hih, *p_hil;
    __nv_bfloat16 *p_wqh, *p_wql, *p_wph, *p_wpl, *p_w1h, *p_w1l, *p_w2h, *p_w2l;
    cudaGetSymbolAddress((void**)&p_x1,  g_x1);
    cudaGetSymbolAddress((void**)&p_bqkv, g_bqkv);
    cudaGetSymbolAddress((void**)&p_xh,  g_xh);   cudaGetSymbolAddress((void**)&p_xl,  g_xl);
    cudaGetSymbolAddress((void**)&p_qh,  g_qh);   cudaGetSymbolAddress((void**)&p_ql,  g_ql);
    cudaGetSymbolAddress((void**)&p_kh,  g_kh);   cudaGetSymbolAddress((void**)&p_kl,  g_kl);
    cudaGetSymbolAddress((void**)&p_vh,  g_vh);   cudaGetSymbolAddress((void**)&p_vl,  g_vl);
    cudaGetSymbolAddress((void**)&p_ath, g_ath);  cudaGetSymbolAddress((void**)&p_atl, g_atl);
    cudaGetSymbolAddress((void**)&p_x1h, g_x1h);  cudaGetSymbolAddress((void**)&p_x1l, g_x1l);
    cudaGetSymbolAddress((void**)&p_hih, g_hih);  cudaGetSymbolAddress((void**)&p_hil, g_hil);
    cudaGetSymbolAddress((void**)&p_wqh, g_wqkv_h); cudaGetSymbolAddress((void**)&p_wql, g_wqkv_l);
    cudaGetSymbolAddress((void**)&p_wph, g_wp_h);   cudaGetSymbolAddress((void**)&p_wpl, g_wp_l);
    cudaGetSymbolAddress((void**)&p_w1h, g_w1_h);   cudaGetSymbolAddress((void**)&p_w1l, g_w1_l);
    cudaGetSymbolAddress((void**)&p_w2h, g_w2_h);   cudaGetSymbolAddress((void**)&p_w2l, g_w2_l);

    cudaFuncSetAttribute(gemm_mma, cudaFuncAttributeMaxDynamicSharedMemorySize, SM_TOTAL);
    cudaFuncSetAttribute(attn_mma, cudaFuncAttributePreferredSharedMemoryCarveout, 100);

    // 1. pack weights + split input activations
    pack_kernel<<<256, 256>>>(Wq, bq, Wk, bk, Wv, bv, Wp, W1, W2);
    split_x_kernel<<<BT_TOTAL * DMODEL / 4 / 256, 256>>>(x, p_xh, p_xl);
    // 2. QKV -> bf16 hi/lo head-major (q pre-scaled by 0.25*log2e for ex2 softmax)
    gemm_mma<<<dim3(256, 3), 256, SM_TOTAL>>>(p_xh, p_xl, 128, p_wqh, p_wql,
                                              p_bqkv, nullptr, nullptr, nullptr,
                                              nullptr, nullptr, nullptr, NQKV, FL_QKV);
    // 3. causal attention (diagonal-balanced) -> bf16 hi/lo
    attn_mma<<<dim3(8, 128), 256>>>(p_qh, p_ql, p_kh, p_kl, p_vh, p_vl, p_ath, p_atl);
    // 4. proj + bias + resid + LN1 -> fp32 x1 + bf16 hi/lo
    gemm_mma<<<dim3(256, 1), 256, SM_TOTAL>>>(p_ath, p_atl, 128, p_wph, p_wpl,
                                              bp, x, g1, be1,
                                              p_x1, p_x1h, p_x1l, DMODEL, FL_LN | FL_F32 | FL_BF);
    // 5. MLP up + GELU -> bf16 hi/lo
    gemm_mma<<<dim3(256, 4), 256, SM_TOTAL>>>(p_x1h, p_x1l, 128, p_w1h, p_w1l,
                                              b1, nullptr, nullptr, nullptr,
                                              nullptr, p_hih, p_hil, FFDIM, FL_GELU | FL_BF);
    // 6. MLP down (K=512) + bias + resid + LN2 -> out
    gemm_mma<<<dim3(256, 1), 256, SM_TOTAL>>>(p_hih, p_hil, 512, p_w2h, p_w2l,
                                              b2, p_x1, g2, be2,
                                              out, nullptr, nullptr, DMODEL, FL_LN | FL_F32);
}

// round 13
// speedup vs baseline: 1.0424x; 1.0424x over previous
#include <cuda_runtime.h>
#include <cuda_bf16.h>
#include <cstdint>
#include <math.h>

// Block_36455682408804: transformer block  B=16 T=1024 D=128 H=8 HS=16 FF=512
#define BT_TOTAL 16384
#define DMODEL   128
#define FFDIM    512
#define NQKV     384

// ---------------------------------------------------------------------------
// device-global scratch (allocation-free, graph-capturable)
// ---------------------------------------------------------------------------
__device__ float g_x1 [BT_TOTAL * DMODEL];                // fp32 residual for MLP2
__device__ float g_bqkv[NQKV];
__device__ __nv_bfloat16 g_xh [BT_TOTAL * DMODEL], g_xl [BT_TOTAL * DMODEL];
__device__ __nv_bfloat16 g_qh [128 * 1024 * 16],   g_ql [128 * 1024 * 16];   // [bh][t][16], pre-scaled 0.25*log2e
__device__ __nv_bfloat16 g_kh [128 * 1024 * 16],   g_kl [128 * 1024 * 16];   // [bh][t][16]
__device__ __nv_bfloat16 g_vh [128 * 1024 * 16],   g_vl [128 * 1024 * 16];   // [bh][t][16]
__device__ __nv_bfloat16 g_ath[BT_TOTAL * DMODEL], g_atl[BT_TOTAL * DMODEL];
__device__ __nv_bfloat16 g_x1h[BT_TOTAL * DMODEL], g_x1l[BT_TOTAL * DMODEL];
__device__ __nv_bfloat16 g_hih[BT_TOTAL * FFDIM],  g_hil[BT_TOTAL * FFDIM];
__device__ __nv_bfloat16 g_wqkv_h[NQKV * DMODEL],  g_wqkv_l[NQKV * DMODEL];
__device__ __nv_bfloat16 g_wp_h[DMODEL * DMODEL],  g_wp_l[DMODEL * DMODEL];
__device__ __nv_bfloat16 g_w1_h[FFDIM * DMODEL],   g_w1_l[FFDIM * DMODEL];
__device__ __nv_bfloat16 g_w2_h[DMODEL * FFDIM],   g_w2_l[DMODEL * FFDIM];

// ---------------------------------------------------------------------------
// helpers
// ---------------------------------------------------------------------------
__device__ __forceinline__ void split_bf(float v, __nv_bfloat16& h, __nv_bfloat16& l) {
    h = __float2bfloat16(v);
    l = __float2bfloat16(v - __bfloat162float(h));
}
__device__ __forceinline__ void split2(float x, float y, uint32_t& h, uint32_t& l) {
    asm("cvt.rn.bf16x2.f32 %0, %1, %2;" : "=r"(h) : "f"(y), "f"(x));
    float xh = __uint_as_float(h << 16);
    float yh = __uint_as_float(h & 0xffff0000u);
    float xl = x - xh, yl = y - yh;
    asm("cvt.rn.bf16x2.f32 %0, %1, %2;" : "=r"(l) : "f"(yl), "f"(xl));
}
__device__ __forceinline__ uint32_t pack2(float x, float y) {
    uint32_t r;
    asm("cvt.rn.bf16x2.f32 %0, %1, %2;" : "=r"(r) : "f"(y), "f"(x));
    return r;
}
__device__ __forceinline__ float ex2f(float x) {
    float r; asm("ex2.approx.f32 %0, %1;" : "=f"(r) : "f"(x)); return r;
}
__device__ __forceinline__ uint32_t smem_u32(const void* p) {
    uint32_t a;
    asm("{ .reg .u64 t; cvta.to.shared.u64 t, %1; cvt.u32.u64 %0, t; }" : "=r"(a) : "l"(p));
    return a;
}
__device__ __forceinline__ void ldsm4(uint32_t addr, uint32_t* r) {
    asm volatile("ldmatrix.sync.aligned.m8n8.x4.shared.b16 {%0,%1,%2,%3}, [%4];"
                 : "=r"(r[0]), "=r"(r[1]), "=r"(r[2]), "=r"(r[3]) : "r"(addr));
}
__device__ __forceinline__ void ldsm4t(uint32_t addr, uint32_t* r) {
    asm volatile("ldmatrix.sync.aligned.m8n8.x4.trans.shared.b16 {%0,%1,%2,%3}, [%4];"
                 : "=r"(r[0]), "=r"(r[1]), "=r"(r[2]), "=r"(r[3]) : "r"(addr));
}
__device__ __forceinline__ void mma_bf16(float* d, const uint32_t* a, uint32_t b0, uint32_t b1) {
    asm volatile("mma.sync.aligned.m16n8k16.row.col.f32.bf16.bf16.f32 "
                 "{%0,%1,%2,%3}, {%4,%5,%6,%7}, {%8,%9}, {%0,%1,%2,%3};"
                 : "+f"(d[0]), "+f"(d[1]), "+f"(d[2]), "+f"(d[3])
                 : "r"(a[0]), "r"(a[1]), "r"(a[2]), "r"(a[3]), "r"(b0), "r"(b1));
}
__device__ __forceinline__ void cp16(uint32_t saddr, const void* gptr) {
    asm volatile("cp.async.cg.shared.global [%0], [%1], 16;" :: "r"(saddr), "l"(gptr));
}
__device__ __forceinline__ void cp_commit() { asm volatile("cp.async.commit_group;"); }
__device__ __forceinline__ void cp_wait0() { asm volatile("cp.async.wait_group 0;"); }
__device__ __forceinline__ void cp_wait1() { asm volatile("cp.async.wait_group 1;"); }
__device__ __forceinline__ float gelu_f(float v) {
    return 0.5f * v * (1.f + erff(v * 0.7071067811865475f));
}

// ---------------------------------------------------------------------------
// pack weights: transpose to [N,K], split bf16 hi/lo
// ---------------------------------------------------------------------------
__global__ void pack_kernel(const float* __restrict__ Wq, const float* __restrict__ bq,
                            const float* __restrict__ Wk, const float* __restrict__ bk,
                            const float* __restrict__ Wv, const float* __restrict__ bv,
                            const float* __restrict__ Wp, const float* __restrict__ W1,
                            const float* __restrict__ W2)
{
    int i0 = blockIdx.x * blockDim.x + threadIdx.x;
    int stride = gridDim.x * blockDim.x;
    for (int i = i0; i < NQKV * DMODEL; i += stride) {
        int n = i >> 7, k = i & 127;
        float v;
        if (n < 128)      v = Wq[((n >> 4) << 11) + k * 16 + (n & 15)];
        else if (n < 256) { int m = n - 128; v = Wk[((m >> 4) << 11) + k * 16 + (m & 15)]; }
        else              { int m = n - 256; v = Wv[((m >> 4) << 11) + k * 16 + (m & 15)]; }
        split_bf(v, g_wqkv_h[i], g_wqkv_l[i]);
    }
    for (int i = i0; i < DMODEL * DMODEL; i += stride) {
        int n = i >> 7, k = i & 127;
        split_bf(Wp[k * 128 + n], g_wp_h[i], g_wp_l[i]);
    }
    for (int i = i0; i < FFDIM * DMODEL; i += stride) {
        int n = i >> 7, k = i & 127;
        split_bf(W1[k * 512 + n], g_w1_h[i], g_w1_l[i]);
    }
    for (int i = i0; i < DMODEL * FFDIM; i += stride) {
        int n = i >> 9, k = i & 511;
        split_bf(W2[k * 128 + n], g_w2_h[i], g_w2_l[i]);
    }
    for (int i = i0; i < NQKV; i += stride)
        g_bqkv[i] = (i < 128) ? bq[i] : (i < 256 ? bk[i - 128] : bv[i - 256]);
}

// split activations x -> xh, xl
__global__ void split_x_kernel(const float* __restrict__ X,
                               __nv_bfloat16* __restrict__ Xh, __nv_bfloat16* __restrict__ Xl)
{
    int i = blockIdx.x * blockDim.x + threadIdx.x;
    float4 v = ((const float4*)X)[i];
    uint32_t h0, l0, h1, l1;
    split2(v.x, v.y, h0, l0); split2(v.z, v.w, h1, l1);
    ((uint2*)Xh)[i] = make_uint2(h0, h1);
    ((uint2*)Xl)[i] = make_uint2(l0, l1);
}

// ---------------------------------------------------------------------------
// HMMA GEMM, all-bf16 inputs, cp.async 2-stage pipeline, 256 threads.
// CTA tile 64x128 (M x N), 8 warps (2m x 4n), warp tile 32x32, K chunk 64.
// flags: 1=gelu, 2=LN(+resid), 4=write fp32, 8=write bf16 hi/lo, 16=QKV layout
// ---------------------------------------------------------------------------
#define FL_GELU 1
#define FL_LN   2
#define FL_F32  4
#define FL_BF   8
#define FL_QKV  16

#define SM_AH 0
#define SM_AL 8192
#define SM_BH 16384
#define SM_BL 32768
#define SM_STAGE 49152
#define SM_CS 0
#define SM_BIAS 98304
#define SM_G    98816
#define SM_BE   99328
#define SM_TOTAL 99840

__global__ __launch_bounds__(256, 2)
void gemm_mma(const __nv_bfloat16* __restrict__ Ah_, const __nv_bfloat16* __restrict__ Al_,
              int K,
              const __nv_bfloat16* __restrict__ Bh_, const __nv_bfloat16* __restrict__ Bl_,
              const float* __restrict__ bias, const float* __restrict__ resid,
              const float* __restrict__ gamma, const float* __restrict__ beta,
              float* __restrict__ Cf, __nv_bfloat16* __restrict__ Cbh, __nv_bfloat16* __restrict__ Cbl,
              int ldc, int flags)
{
    extern __shared__ unsigned char smraw[];
    const uint32_t smem_base = smem_u32(smraw);
    float* sBias = (float*)(smraw + SM_BIAS);
    float* sG    = (float*)(smraw + SM_G);
    float* sBe   = (float*)(smraw + SM_BE);
    float* Cs    = (float*)(smraw + SM_CS);

    const int tid = threadIdx.x;
    const int wid = tid >> 5, lane = tid & 31;
    const int m0 = blockIdx.x * 64, n0 = blockIdx.y * 128;
    const int wm = (wid & 1) * 32, wn = (wid >> 1) * 32;

    if (tid < 128) {
        sBias[tid] = bias[n0 + tid];
        if (flags & FL_LN) { sG[tid] = gamma[tid]; sBe[tid] = beta[tid]; }
    }

    const int q = lane >> 3, rin = lane & 7;
    const int rowA0 = wm + (q & 1) * 8 + rin;
    const int kqoff = (q >> 1) * 16;

    const int ar = tid >> 2, aq = tid & 3;
    const int br = tid >> 1, bq2 = tid & 1;
    const uint32_t aswz = (uint32_t)(ar & 7) << 4;
    const uint32_t bswz = (uint32_t)(br & 7) << 4;

    float acc[2][4][4];
    #pragma unroll
    for (int i = 0; i < 2; ++i)
        #pragma unroll
        for (int j = 0; j < 4; ++j)
            #pragma unroll
            for (int e = 0; e < 4; ++e) acc[i][j][e] = 0.f;

    const int nchunks = K >> 6;
    const size_t arow = (size_t)(m0 + ar) * K;
    const size_t brow = (size_t)(n0 + br) * K;

    {
        #pragma unroll
        for (int g = 0; g < 2; ++g) {
            int slot = aq * 2 + g;
            uint32_t off = (uint32_t)ar * 128 + (((uint32_t)slot * 16) ^ aswz);
            cp16(smem_base + SM_AH + off, Ah_ + arow + slot * 8);
            cp16(smem_base + SM_AL + off, Al_ + arow + slot * 8);
        }
        #pragma unroll
        for (int g = 0; g < 4; ++g) {
            int slot = bq2 * 4 + g;
            uint32_t off = (uint32_t)br * 128 + (((uint32_t)slot * 16) ^ bswz);
            cp16(smem_base + SM_BH + off, Bh_ + brow + slot * 8);
            cp16(smem_base + SM_BL + off, Bl_ + brow + slot * 8);
        }
        cp_commit();
    }

    for (int c = 0; c < nchunks; ++c) {
        if (c + 1 < nchunks) {
            const int kc = (c + 1) << 6;
            const uint32_t sb = smem_base + ((c + 1) & 1) * SM_STAGE;
            #pragma unroll
            for (int g = 0; g < 2; ++g) {
                int slot = aq * 2 + g;
                uint32_t off = (uint32_t)ar * 128 + (((uint32_t)slot * 16) ^ aswz);
                cp16(sb + SM_AH + off, Ah_ + arow + kc + slot * 8);
                cp16(sb + SM_AL + off, Al_ + arow + kc + slot * 8);
            }
            #pragma unroll
            for (int g = 0; g < 4; ++g) {
                int slot = bq2 * 4 + g;
                uint32_t off = (uint32_t)br * 128 + (((uint32_t)slot * 16) ^ bswz);
                cp16(sb + SM_BH + off, Bh_ + brow + kc + slot * 8);
                cp16(sb + SM_BL + off, Bl_ + brow + kc + slot * 8);
            }
            cp_commit();
            cp_wait1();
        } else {
            cp_wait0();
        }
        __syncthreads();
        const uint32_t sb = smem_base + (c & 1) * SM_STAGE;
        #pragma unroll
        for (int ks = 0; ks < 4; ++ks) {
            const uint32_t kb = (uint32_t)(ks * 32 + kqoff);
            uint32_t ah[2][4], al[2][4], bh[4][2], bl[4][2];
            #pragma unroll
            for (int i = 0; i < 2; ++i) {
                uint32_t row = (uint32_t)(rowA0 + i * 16);
                uint32_t off = row * 128 + (kb ^ ((row & 7) << 4));
                ldsm4(sb + SM_AH + off, ah[i]);
                ldsm4(sb + SM_AL + off, al[i]);
            }
            #pragma unroll
            for (int j2 = 0; j2 < 2; ++j2) {
                uint32_t row = (uint32_t)(wn + j2 * 16 + (q & 1) * 8 + rin);
                uint32_t off = row * 128 + (kb ^ ((row & 7) << 4));
                uint32_t r4v[4];
                ldsm4(sb + SM_BH + off, r4v);
                bh[2*j2][0] = r4v[0]; bh[2*j2][1] = r4v[2];
                bh[2*j2+1][0] = r4v[1]; bh[2*j2+1][1] = r4v[3];
                ldsm4(sb + SM_BL + off, r4v);
                bl[2*j2][0] = r4v[0]; bl[2*j2][1] = r4v[2];
                bl[2*j2+1][0] = r4v[1]; bl[2*j2+1][1] = r4v[3];
            }
            #pragma unroll
            for (int i = 0; i < 2; ++i)
                #pragma unroll
                for (int j = 0; j < 4; ++j) {
                    mma_bf16(acc[i][j], ah[i], bh[j][0], bh[j][1]);
                    mma_bf16(acc[i][j], ah[i], bl[j][0], bl[j][1]);
                    mma_bf16(acc[i][j], al[i], bh[j][0], bh[j][1]);
                }
        }
        __syncthreads();
    }

    if (flags & FL_QKV) {
        __nv_bfloat16 *dsth, *dstl;
        float scale;
        if (n0 == 0)        { dsth = g_qh; dstl = g_ql; scale = 0.36067376022224085f; }  // 0.25*log2(e)
        else if (n0 == 128) { dsth = g_kh; dstl = g_kl; scale = 1.f; }
        else                { dsth = g_vh; dstl = g_vl; scale = 1.f; }
        #pragma unroll
        for (int i = 0; i < 2; ++i)
            #pragma unroll
            for (int j = 0; j < 4; ++j) {
                int cp = wn + j * 8 + (lane & 3) * 2;
                float b0 = sBias[cp], b1 = sBias[cp + 1];
                int hh8 = (cp >> 4) & 7, e = cp & 15;
                #pragma unroll
                for (int rr = 0; rr < 2; ++rr) {
                    int r = m0 + wm + i * 16 + (lane >> 2) + rr * 8;
                    float v0 = (acc[i][j][rr * 2 + 0] + b0) * scale;
                    float v1 = (acc[i][j][rr * 2 + 1] + b1) * scale;
                    int bb = r >> 10, t = r & 1023;
                    int bh128 = bb * 8 + hh8;
                    uint32_t hh, ll;
                    split2(v0, v1, hh, ll);
                    size_t idx = ((size_t)bh128 * 1024 + t) * 16 + e;
                    *(uint32_t*)(dsth + idx) = hh;
                    *(uint32_t*)(dstl + idx) = ll;
                }
            }
    } else if (!(flags & FL_LN)) {
        #pragma unroll
        for (int i = 0; i < 2; ++i)
            #pragma unroll
            for (int j = 0; j < 4; ++j) {
                int cp = wn + j * 8 + (lane & 3) * 2;
                float b0 = sBias[cp], b1 = sBias[cp + 1];
                int r0 = m0 + wm + i * 16 + (lane >> 2);
                float v0 = acc[i][j][0] + b0, v1 = acc[i][j][1] + b1;
                float v2 = acc[i][j][2] + b0, v3 = acc[i][j][3] + b1;
                if (flags & FL_GELU) { v0 = gelu_f(v0); v1 = gelu_f(v1); v2 = gelu_f(v2); v3 = gelu_f(v3); }
                if (flags & FL_F32) {
                    *(float2*)(Cf + (size_t)r0 * ldc + n0 + cp)       = make_float2(v0, v1);
                    *(float2*)(Cf + (size_t)(r0 + 8) * ldc + n0 + cp) = make_float2(v2, v3);
                }
                if (flags & FL_BF) {
                    uint32_t hh, ll;
                    split2(v0, v1, hh, ll);
                    *(uint32_t*)(Cbh + (size_t)r0 * ldc + n0 + cp) = hh;
                    *(uint32_t*)(Cbl + (size_t)r0 * ldc + n0 + cp) = ll;
                    split2(v2, v3, hh, ll);
                    *(uint32_t*)(Cbh + (size_t)(r0 + 8) * ldc + n0 + cp) = hh;
                    *(uint32_t*)(Cbl + (size_t)(r0 + 8) * ldc + n0 + cp) = ll;
                }
            }
    } else {
        #pragma unroll
        for (int i = 0; i < 2; ++i)
            #pragma unroll
            for (int j = 0; j < 4; ++j) {
                int cp = wn + j * 8 + (lane & 3) * 2;
                float b0 = sBias[cp], b1 = sBias[cp + 1];
                int r0 = wm + i * 16 + (lane >> 2);
                Cs[r0 * 132 + cp]           = acc[i][j][0] + b0;
                Cs[r0 * 132 + cp + 1]       = acc[i][j][1] + b1;
                Cs[(r0 + 8) * 132 + cp]     = acc[i][j][2] + b0;
                Cs[(r0 + 8) * 132 + cp + 1] = acc[i][j][3] + b1;
            }
        __syncthreads();
        for (int rr = 0; rr < 8; ++rr) {
            int row = wid * 8 + rr;
            const float* cr = Cs + row * 132 + lane * 4;
            float2 p0 = *(const float2*)(cr);
            float2 p1 = *(const float2*)(cr + 2);
            const float4 rv = *(const float4*)(resid + (size_t)(m0 + row) * 128 + lane * 4);
            float v0 = p0.x + rv.x, v1 = p0.y + rv.y, v2 = p1.x + rv.z, v3 = p1.y + rv.w;
            float s  = v0 + v1 + v2 + v3;
            float sq2 = v0 * v0 + v1 * v1 + v2 * v2 + v3 * v3;
            #pragma unroll
            for (int off = 16; off > 0; off >>= 1) {
                s   += __shfl_xor_sync(0xffffffffu, s,   off);
                sq2 += __shfl_xor_sync(0xffffffffu, sq2, off);
            }
            float mean = s * (1.f / 128.f);
            float var  = sq2 * (1.f / 128.f) - mean * mean;
            float is   = rsqrtf(var + 1e-5f);
            int cb = lane * 4;
            float o0 = (v0 - mean) * is * sG[cb]     + sBe[cb];
            float o1 = (v1 - mean) * is * sG[cb + 1] + sBe[cb + 1];
            float o2 = (v2 - mean) * is * sG[cb + 2] + sBe[cb + 2];
            float o3 = (v3 - mean) * is * sG[cb + 3] + sBe[cb + 3];
            size_t base = (size_t)(m0 + row) * 128 + cb;
            if (flags & FL_F32)
                *(float4*)(Cf + base) = make_float4(o0, o1, o2, o3);
            if (flags & FL_BF) {
                uint32_t hh, ll;
                split2(o0, o1, hh, ll);
                *(uint32_t*)(Cbh + base) = hh; *(uint32_t*)(Cbl + base) = ll;
                split2(o2, o3, hh, ll);
                *(uint32_t*)(Cbh + base + 2) = hh; *(uint32_t*)(Cbl + base + 2) = ll;
            }
        }
    }
}

// ---------------------------------------------------------------------------
// Flash-style causal attention via HMMA, DIAGONAL-BALANCED, 8 warps/CTA,
// cp.async double-buffered K/V staging. ex2-domain softmax (Q pre-scaled).
// P stored as plain bf16 (normalization cancels common-mode rounding);
// P@V = 2 mmas (ph*vh + ph*vl). Q@K stays 3-mma exact.
// ---------------------------------------------------------------------------
struct TileAcc {
    float o[2][4];
    float lsum[2];
};

__device__ __forceinline__ void attn_step(
    const uint32_t* aqh, const uint32_t* aql,
    const uint32_t* kfh, const uint32_t* kfl,
    int kbase, int W, int r4, int c2,
    const uint32_t* vbh, const uint32_t* vbl,
    TileAcc& T)
{
    float s[2][4];
    #pragma unroll
    for (int jj = 0; jj < 2; ++jj)
        #pragma unroll
        for (int e = 0; e < 4; ++e) s[jj][e] = 0.f;
    #pragma unroll
    for (int jj = 0; jj < 2; ++jj) {
        uint32_t kb0 = kfh[jj], kb1 = kfh[2 + jj];
        uint32_t kl0 = kfl[jj], kl1 = kfl[2 + jj];
        mma_bf16(s[jj], aqh, kb0, kb1);
        mma_bf16(s[jj], aqh, kl0, kl1);
        mma_bf16(s[jj], aql, kb0, kb1);
    }
    uint32_t pa[4];
    const bool full = (kbase + 15 <= W);
    const int t0 = W + r4, t1 = t0 + 8;
    #pragma unroll
    for (int jj = 0; jj < 2; ++jj) {
        int ub = kbase + jj * 8 + c2;
        float p0 = ex2f(s[jj][0]);
        float p1 = ex2f(s[jj][1]);
        float p2 = ex2f(s[jj][2]);
        float p3 = ex2f(s[jj][3]);
        if (!full) {
            if (ub > t0)     p0 = 0.f;
            if (ub + 1 > t0) p1 = 0.f;
            if (ub > t1)     p2 = 0.f;
            if (ub + 1 > t1) p3 = 0.f;
        }
        T.lsum[0] += p0 + p1;
        T.lsum[1] += p2 + p3;
        pa[jj * 2 + 0] = pack2(p0, p1);
        pa[jj * 2 + 1] = pack2(p2, p3);
    }
    #pragma unroll
    for (int nt = 0; nt < 2; ++nt) {
        mma_bf16(T.o[nt], pa, vbh[nt * 2], vbh[nt * 2 + 1]);
        mma_bf16(T.o[nt], pa, vbl[nt * 2], vbl[nt * 2 + 1]);
    }
}

__global__ __launch_bounds__(256)
void attn_mma(const __nv_bfloat16* __restrict__ Qh, const __nv_bfloat16* __restrict__ Ql,
              const __nv_bfloat16* __restrict__ Kh, const __nv_bfloat16* __restrict__ Kl,
              const __nv_bfloat16* __restrict__ Vh, const __nv_bfloat16* __restrict__ Vl,
              __nv_bfloat16* __restrict__ Oh, __nv_bfloat16* __restrict__ Ol)
{
    __shared__ __align__(16) __nv_bfloat16 sKh[2][128 * 24], sKl[2][128 * 24];
    __shared__ __align__(16) __nv_bfloat16 sVh[2][128 * 24], sVl[2][128 * 24];

    const int pa_ = blockIdx.x;
    const int bh = blockIdx.y;
    const int a = pa_, bqt = 15 - pa_;
    const int tid = threadIdx.x;
    const int w = tid >> 5, lane = tid & 31;
    const int wg = w >> 2, wi = w & 3;
    const int myqt = wg ? bqt : a;
    const int W = myqt * 64 + wi * 16;
    const int r4 = lane >> 2, c2 = (lane & 3) * 2;
    const uint32_t skh0 = smem_u32(sKh[0]), skl0 = smem_u32(sKl[0]);
    const uint32_t skh1 = smem_u32(sKh[1]), skl1 = smem_u32(sKl[1]);
    const uint32_t svh0 = smem_u32(sVh[0]), svl0 = smem_u32(sVl[0]);
    const uint32_t svh1 = smem_u32(sVh[1]), svl1 = smem_u32(sVl[1]);

    const int mi = lane >> 3, li = lane & 7;
    const uint32_t vfrag_off = (uint32_t)(((li + (mi & 1) * 8) * 24 + (mi >> 1) * 8) * 2);
    const uint32_t kfrag_off = (uint32_t)(((mi & 1) * 8 + li) * 48 + (mi >> 1) * 16);

    if (tid < 128) {
        int qrow = (tid < 64) ? (a * 64 + tid) : (bqt * 64 + tid - 64);
        const __nv_bfloat16* srcH = Qh + ((size_t)bh * 1024 + qrow) * 16;
        const __nv_bfloat16* srcL = Ql + ((size_t)bh * 1024 + qrow) * 16;
        *(uint4*)&sKh[0][tid * 24]     = ((const uint4*)srcH)[0];
        *(uint4*)&sKh[0][tid * 24 + 8] = ((const uint4*)srcH)[1];
        *(uint4*)&sKl[0][tid * 24]     = ((const uint4*)srcL)[0];
        *(uint4*)&sKl[0][tid * 24 + 8] = ((const uint4*)srcL)[1];
    }
    __syncthreads();

    uint32_t aqh[4], aql[4];
    {
        uint32_t row = (uint32_t)(wg * 64 + wi * 16 + (mi & 1) * 8 + li);
        uint32_t boff = row * 48 + (uint32_t)(mi >> 1) * 16;
        ldsm4(skh0 + boff, aqh);
        ldsm4(skl0 + boff, aql);
    }
    __syncthreads();

    TileAcc T;
    #pragma unroll
    for (int nt = 0; nt < 2; ++nt)
        #pragma unroll
        for (int e = 0; e < 4; ++e) T.o[nt][e] = 0.f;
    T.lsum[0] = T.lsum[1] = 0.f;

    const int strow = tid >> 1, sthalf = tid & 1;
    const uint32_t stoff = (uint32_t)strow * 48 + (uint32_t)sthalf * 16;
    const size_t stg_base = ((size_t)bh * 1024 + strow) * 16 + sthalf * 8;

    const int ntiles = (bqt + 2) >> 1;
    {
        const size_t goff = stg_base;
        cp16(skh0 + stoff, Kh + goff);
        cp16(skl0 + stoff, Kl + goff);
        cp16(svh0 + stoff, Vh + goff);
        cp16(svl0 + stoff, Vl + goff);
        cp_commit();
    }

    for (int tile = 0; tile < ntiles; ++tile) {
        if (tile + 1 < ntiles) {
            const size_t goff = stg_base + (size_t)((tile + 1) << 7) * 16;
            const uint32_t kh = ((tile + 1) & 1) ? skh1 : skh0;
            const uint32_t kl = ((tile + 1) & 1) ? skl1 : skl0;
            const uint32_t vh = ((tile + 1) & 1) ? svh1 : svh0;
            const uint32_t vl = ((tile + 1) & 1) ? svl1 : svl0;
            cp16(kh + stoff, Kh + goff);
            cp16(kl + stoff, Kl + goff);
            cp16(vh + stoff, Vh + goff);
            cp16(vl + stoff, Vl + goff);
            cp_commit();
            cp_wait1();
        } else {
            cp_wait0();
        }
        __syncthreads();
        const int bi = tile & 1;
        const uint32_t ckh = bi ? skh1 : skh0;
        const uint32_t ckl = bi ? skl1 : skl0;
        const uint32_t cvh = bi ? svh1 : svh0;
        const uint32_t cvl = bi ? svl1 : svl0;
        const int u0 = tile << 7;

        if (u0 <= W + 15) {
            #pragma unroll
            for (int kk = 0; kk < 8; ++kk) {
                const int kbase = u0 + kk * 16;
                if (kbase > W + 15) break;
                uint32_t vbh[4], vbl[4], kfh[4], kfl[4];
                uint32_t tileoff = (uint32_t)(kk * 16 * 48);
                ldsm4t(cvh + vfrag_off + tileoff, vbh);
                ldsm4t(cvl + vfrag_off + tileoff, vbl);
                ldsm4(ckh + kfrag_off + tileoff, kfh);
                ldsm4(ckl + kfrag_off + tileoff, kfl);
                attn_step(aqh, aql, kfh, kfl, kbase, W, r4, c2, vbh, vbl, T);
            }
        }
        __syncthreads();
    }

    const int b = bh >> 3, h = bh & 7;
    const int bT = b << 10;
    {
        float l0 = T.lsum[0], l1 = T.lsum[1];
        l0 += __shfl_xor_sync(0xffffffffu, l0, 1);
        l0 += __shfl_xor_sync(0xffffffffu, l0, 2);
        l1 += __shfl_xor_sync(0xffffffffu, l1, 1);
        l1 += __shfl_xor_sync(0xffffffffu, l1, 2);
        float i0 = 1.f / l0, i1 = 1.f / l1;
        int row0 = bT + W + r4;
        #pragma unroll
        for (int nt = 0; nt < 2; ++nt) {
            int col = (h << 4) + nt * 8 + c2;
            uint32_t hh, ll;
            split2(T.o[nt][0] * i0, T.o[nt][1] * i0, hh, ll);
            *(uint32_t*)(Oh + (size_t)row0 * 128 + col) = hh;
            *(uint32_t*)(Ol + (size_t)row0 * 128 + col) = ll;
            split2(T.o[nt][2] * i1, T.o[nt][3] * i1, hh, ll);
            *(uint32_t*)(Oh + (size_t)(row0 + 8) * 128 + col) = hh;
            *(uint32_t*)(Ol + (size_t)(row0 + 8) * 128 + col) = ll;
        }
    }
}

// ---------------------------------------------------------------------------
extern "C" void kernel_launch(void* const* d_in, const int* in_sizes, int n_in,
                              void* d_out, int out_size)
{
    const float* x   = (const float*)d_in[0];
    const float* Wq  = (const float*)d_in[1];
    const float* bq  = (const float*)d_in[2];
    const float* Wk  = (const float*)d_in[3];
    const float* bk  = (const float*)d_in[4];
    const float* Wv  = (const float*)d_in[5];
    const float* bv  = (const float*)d_in[6];
    const float* Wp  = (const float*)d_in[7];
    const float* bp  = (const float*)d_in[8];
    const float* W1  = (const float*)d_in[9];
    const float* b1  = (const float*)d_in[10];
    const float* W2  = (const float*)d_in[11];
    const float* b2  = (const float*)d_in[12];
    const float* g1  = (const float*)d_in[13];
    const float* be1 = (const float*)d_in[14];
    const float* g2  = (const float*)d_in[15];
    const float* be2 = (const float*)d_in[16];
    float* out = (float*)d_out;

    float *p_x1, *p_bqkv;
    __nv_bfloat16 *p_xh, *p_xl, *p_qh, *p_ql, *p_kh, *p_kl, *p_vh, *p_vl;
    __nv_bfloat16 *p_ath, *p_atl, *p_x1h, *p_x1l, *p_hih, *p_hil;
    __nv_bfloat16 *p_wqh, *p_wql, *p_wph, *p_wpl, *p_w1h, *p_w1l, *p_w2h, *p_w2l;
    cudaGetSymbolAddress((void**)&p_x1,  g_x1);
    cudaGetSymbolAddress((void**)&p_bqkv, g_bqkv);
    cudaGetSymbolAddress((void**)&p_xh,  g_xh);   cudaGetSymbolAddress((void**)&p_xl,  g_xl);
    cudaGetSymbolAddress((void**)&p_qh,  g_qh);   cudaGetSymbolAddress((void**)&p_ql,  g_ql);
    cudaGetSymbolAddress((void**)&p_kh,  g_kh);   cudaGetSymbolAddress((void**)&p_kl,  g_kl);
    cudaGetSymbolAddress((void**)&p_vh,  g_vh);   cudaGetSymbolAddress((void**)&p_vl,  g_vl);
    cudaGetSymbolAddress((void**)&p_ath, g_ath);  cudaGetSymbolAddress((void**)&p_atl, g_atl);
    cudaGetSymbolAddress((void**)&p_x1h, g_x1h);  cudaGetSymbolAddress((void**)&p_x1l, g_x1l);
    cudaGetSymbolAddress((void**)&p_hih, g_hih);  cudaGetSymbolAddress((void**)&p_hil, g_hil);
    cudaGetSymbolAddress((void**)&p_wqh, g_wqkv_h); cudaGetSymbolAddress((void**)&p_wql, g_wqkv_l);
    cudaGetSymbolAddress((void**)&p_wph, g_wp_h);   cudaGetSymbolAddress((void**)&p_wpl, g_wp_l);
    cudaGetSymbolAddress((void**)&p_w1h, g_w1_h);   cudaGetSymbolAddress((void**)&p_w1l, g_w1_l);
    cudaGetSymbolAddress((void**)&p_w2h, g_w2_h);   cudaGetSymbolAddress((void**)&p_w2l, g_w2_l);

    cudaFuncSetAttribute(gemm_mma, cudaFuncAttributeMaxDynamicSharedMemorySize, SM_TOTAL);

    // 1. pack weights + split input activations
    pack_kernel<<<256, 256>>>(Wq, bq, Wk, bk, Wv, bv, Wp, W1, W2);
    split_x_kernel<<<BT_TOTAL * DMODEL / 4 / 256, 256>>>(x, p_xh, p_xl);
    // 2. QKV -> bf16 hi/lo head-major (q pre-scaled by 0.25*log2e for ex2 softmax)
    gemm_mma<<<dim3(256, 3), 256, SM_TOTAL>>>(p_xh, p_xl, 128, p_wqh, p_wql,
                                              p_bqkv, nullptr, nullptr, nullptr,
                                              nullptr, nullptr, nullptr, NQKV, FL_QKV);
    // 3. causal attention (diagonal-balanced) -> bf16 hi/lo
    attn_mma<<<dim3(8, 128), 256>>>(p_qh, p_ql, p_kh, p_kl, p_vh, p_vl, p_ath, p_atl);
    // 4. proj + bias + resid + LN1 -> fp32 x1 + bf16 hi/lo
    gemm_mma<<<dim3(256, 1), 256, SM_TOTAL>>>(p_ath, p_atl, 128, p_wph, p_wpl,
                                              bp, x, g1, be1,
                                              p_x1, p_x1h, p_x1l, DMODEL, FL_LN | FL_F32 | FL_BF);
    // 5. MLP up + GELU -> bf16 hi/lo
    gemm_mma<<<dim3(256, 4), 256, SM_TOTAL>>>(p_x1h, p_x1l, 128, p_w1h, p_w1l,
                                              b1, nullptr, nullptr, nullptr,
                                              nullptr, p_hih, p_hil, FFDIM, FL_GELU | FL_BF);
    // 6. MLP down (K=512) + bias + resid + LN2 -> out
    gemm_mma<<<dim3(256, 1), 256, SM_TOTAL>>>(p_hih, p_hil, 512, p_w2h, p_w2l,
                                              b2, p_x1, g2, be2,
                                              out, nullptr, nullptr, DMODEL, FL_LN | FL_F32);
}

// round 14
// speedup vs baseline: 1.1122x; 1.0670x over previous
#include <cuda_runtime.h>
#include <cuda_bf16.h>
#include <cstdint>
#include <math.h>

// Block_36455682408804: transformer block  B=16 T=1024 D=128 H=8 HS=16 FF=512
#define BT_TOTAL 16384
#define DMODEL   128
#define FFDIM    512
#define NQKV     384

// ---------------------------------------------------------------------------
// device-global scratch (allocation-free, graph-capturable)
// ---------------------------------------------------------------------------
__device__ float g_x1 [BT_TOTAL * DMODEL];                // fp32 residual for MLP2
__device__ float g_bqkv[NQKV];
__device__ __nv_bfloat16 g_xh [BT_TOTAL * DMODEL], g_xl [BT_TOTAL * DMODEL];
__device__ __nv_bfloat16 g_qh [128 * 1024 * 16],   g_ql [128 * 1024 * 16];   // [bh][t][16], pre-scaled 0.25*log2e
__device__ __nv_bfloat16 g_kh [128 * 1024 * 16],   g_kl [128 * 1024 * 16];   // [bh][t][16]
__device__ __nv_bfloat16 g_vh [128 * 1024 * 16];                              // [bh][t][16] single bf16
__device__ __nv_bfloat16 g_ath[BT_TOTAL * DMODEL], g_atl[BT_TOTAL * DMODEL];
__device__ __nv_bfloat16 g_x1h[BT_TOTAL * DMODEL], g_x1l[BT_TOTAL * DMODEL];
__device__ __nv_bfloat16 g_hih[BT_TOTAL * FFDIM],  g_hil[BT_TOTAL * FFDIM];
__device__ __nv_bfloat16 g_wqkv_h[NQKV * DMODEL],  g_wqkv_l[NQKV * DMODEL];
__device__ __nv_bfloat16 g_wp_h[DMODEL * DMODEL],  g_wp_l[DMODEL * DMODEL];
__device__ __nv_bfloat16 g_w1_h[FFDIM * DMODEL],   g_w1_l[FFDIM * DMODEL];
__device__ __nv_bfloat16 g_w2_h[DMODEL * FFDIM],   g_w2_l[DMODEL * FFDIM];

// ---------------------------------------------------------------------------
// helpers
// ---------------------------------------------------------------------------
__device__ __forceinline__ void split_bf(float v, __nv_bfloat16& h, __nv_bfloat16& l) {
    h = __float2bfloat16(v);
    l = __float2bfloat16(v - __bfloat162float(h));
}
__device__ __forceinline__ void split2(float x, float y, uint32_t& h, uint32_t& l) {
    asm("cvt.rn.bf16x2.f32 %0, %1, %2;" : "=r"(h) : "f"(y), "f"(x));
    float xh = __uint_as_float(h << 16);
    float yh = __uint_as_float(h & 0xffff0000u);
    float xl = x - xh, yl = y - yh;
    asm("cvt.rn.bf16x2.f32 %0, %1, %2;" : "=r"(l) : "f"(yl), "f"(xl));
}
__device__ __forceinline__ uint32_t pack2(float x, float y) {
    uint32_t r;
    asm("cvt.rn.bf16x2.f32 %0, %1, %2;" : "=r"(r) : "f"(y), "f"(x));
    return r;
}
__device__ __forceinline__ float ex2f(float x) {
    float r; asm("ex2.approx.f32 %0, %1;" : "=f"(r) : "f"(x)); return r;
}
__device__ __forceinline__ uint32_t smem_u32(const void* p) {
    uint32_t a;
    asm("{ .reg .u64 t; cvta.to.shared.u64 t, %1; cvt.u32.u64 %0, t; }" : "=r"(a) : "l"(p));
    return a;
}
__device__ __forceinline__ void ldsm4(uint32_t addr, uint32_t* r) {
    asm volatile("ldmatrix.sync.aligned.m8n8.x4.shared.b16 {%0,%1,%2,%3}, [%4];"
                 : "=r"(r[0]), "=r"(r[1]), "=r"(r[2]), "=r"(r[3]) : "r"(addr));
}
__device__ __forceinline__ void ldsm4t(uint32_t addr, uint32_t* r) {
    asm volatile("ldmatrix.sync.aligned.m8n8.x4.trans.shared.b16 {%0,%1,%2,%3}, [%4];"
                 : "=r"(r[0]), "=r"(r[1]), "=r"(r[2]), "=r"(r[3]) : "r"(addr));
}
__device__ __forceinline__ void mma_bf16(float* d, const uint32_t* a, uint32_t b0, uint32_t b1) {
    asm volatile("mma.sync.aligned.m16n8k16.row.col.f32.bf16.bf16.f32 "
                 "{%0,%1,%2,%3}, {%4,%5,%6,%7}, {%8,%9}, {%0,%1,%2,%3};"
                 : "+f"(d[0]), "+f"(d[1]), "+f"(d[2]), "+f"(d[3])
                 : "r"(a[0]), "r"(a[1]), "r"(a[2]), "r"(a[3]), "r"(b0), "r"(b1));
}
__device__ __forceinline__ void cp16(uint32_t saddr, const void* gptr) {
    asm volatile("cp.async.cg.shared.global [%0], [%1], 16;" :: "r"(saddr), "l"(gptr));
}
__device__ __forceinline__ void cp_commit() { asm volatile("cp.async.commit_group;"); }
__device__ __forceinline__ void cp_wait0() { asm volatile("cp.async.wait_group 0;"); }
__device__ __forceinline__ void cp_wait1() { asm volatile("cp.async.wait_group 1;"); }
__device__ __forceinline__ float gelu_f(float v) {
    return 0.5f * v * (1.f + erff(v * 0.7071067811865475f));
}

// ---------------------------------------------------------------------------
// pack weights: transpose to [N,K], split bf16 hi/lo
// ---------------------------------------------------------------------------
__global__ void pack_kernel(const float* __restrict__ Wq, const float* __restrict__ bq,
                            const float* __restrict__ Wk, const float* __restrict__ bk,
                            const float* __restrict__ Wv, const float* __restrict__ bv,
                            const float* __restrict__ Wp, const float* __restrict__ W1,
                            const float* __restrict__ W2)
{
    int i0 = blockIdx.x * blockDim.x + threadIdx.x;
    int stride = gridDim.x * blockDim.x;
    for (int i = i0; i < NQKV * DMODEL; i += stride) {
        int n = i >> 7, k = i & 127;
        float v;
        if (n < 128)      v = Wq[((n >> 4) << 11) + k * 16 + (n & 15)];
        else if (n < 256) { int m = n - 128; v = Wk[((m >> 4) << 11) + k * 16 + (m & 15)]; }
        else              { int m = n - 256; v = Wv[((m >> 4) << 11) + k * 16 + (m & 15)]; }
        split_bf(v, g_wqkv_h[i], g_wqkv_l[i]);
    }
    for (int i = i0; i < DMODEL * DMODEL; i += stride) {
        int n = i >> 7, k = i & 127;
        split_bf(Wp[k * 128 + n], g_wp_h[i], g_wp_l[i]);
    }
    for (int i = i0; i < FFDIM * DMODEL; i += stride) {
        int n = i >> 7, k = i & 127;
        split_bf(W1[k * 512 + n], g_w1_h[i], g_w1_l[i]);
    }
    for (int i = i0; i < DMODEL * FFDIM; i += stride) {
        int n = i >> 9, k = i & 511;
        split_bf(W2[k * 128 + n], g_w2_h[i], g_w2_l[i]);
    }
    for (int i = i0; i < NQKV; i += stride)
        g_bqkv[i] = (i < 128) ? bq[i] : (i < 256 ? bk[i - 128] : bv[i - 256]);
}

// split activations x -> xh, xl
__global__ void split_x_kernel(const float* __restrict__ X,
                               __nv_bfloat16* __restrict__ Xh, __nv_bfloat16* __restrict__ Xl)
{
    int i = blockIdx.x * blockDim.x + threadIdx.x;
    float4 v = ((const float4*)X)[i];
    uint32_t h0, l0, h1, l1;
    split2(v.x, v.y, h0, l0); split2(v.z, v.w, h1, l1);
    ((uint2*)Xh)[i] = make_uint2(h0, h1);
    ((uint2*)Xl)[i] = make_uint2(l0, l1);
}

// ---------------------------------------------------------------------------
// HMMA GEMM, all-bf16 inputs, cp.async 2-stage pipeline, 256 threads.
// CTA tile 64x128 (M x N), 8 warps (2m x 4n), warp tile 32x32, K chunk 64.
// flags: 1=gelu, 2=LN(+resid), 4=write fp32, 8=write bf16 hi/lo, 16=QKV layout
// ---------------------------------------------------------------------------
#define FL_GELU 1
#define FL_LN   2
#define FL_F32  4
#define FL_BF   8
#define FL_QKV  16

#define SM_AH 0
#define SM_AL 8192
#define SM_BH 16384
#define SM_BL 32768
#define SM_STAGE 49152
#define SM_CS 0
#define SM_BIAS 98304
#define SM_G    98816
#define SM_BE   99328
#define SM_TOTAL 99840

__global__ __launch_bounds__(256, 2)
void gemm_mma(const __nv_bfloat16* __restrict__ Ah_, const __nv_bfloat16* __restrict__ Al_,
              int K,
              const __nv_bfloat16* __restrict__ Bh_, const __nv_bfloat16* __restrict__ Bl_,
              const float* __restrict__ bias, const float* __restrict__ resid,
              const float* __restrict__ gamma, const float* __restrict__ beta,
              float* __restrict__ Cf, __nv_bfloat16* __restrict__ Cbh, __nv_bfloat16* __restrict__ Cbl,
              int ldc, int flags)
{
    extern __shared__ unsigned char smraw[];
    const uint32_t smem_base = smem_u32(smraw);
    float* sBias = (float*)(smraw + SM_BIAS);
    float* sG    = (float*)(smraw + SM_G);
    float* sBe   = (float*)(smraw + SM_BE);
    float* Cs    = (float*)(smraw + SM_CS);

    const int tid = threadIdx.x;
    const int wid = tid >> 5, lane = tid & 31;
    const int m0 = blockIdx.x * 64, n0 = blockIdx.y * 128;
    const int wm = (wid & 1) * 32, wn = (wid >> 1) * 32;

    if (tid < 128) {
        sBias[tid] = bias[n0 + tid];
        if (flags & FL_LN) { sG[tid] = gamma[tid]; sBe[tid] = beta[tid]; }
    }

    const int q = lane >> 3, rin = lane & 7;
    const int rowA0 = wm + (q & 1) * 8 + rin;
    const int kqoff = (q >> 1) * 16;

    const int ar = tid >> 2, aq = tid & 3;
    const int br = tid >> 1, bq2 = tid & 1;
    const uint32_t aswz = (uint32_t)(ar & 7) << 4;
    const uint32_t bswz = (uint32_t)(br & 7) << 4;

    float acc[2][4][4];
    #pragma unroll
    for (int i = 0; i < 2; ++i)
        #pragma unroll
        for (int j = 0; j < 4; ++j)
            #pragma unroll
            for (int e = 0; e < 4; ++e) acc[i][j][e] = 0.f;

    const int nchunks = K >> 6;
    const size_t arow = (size_t)(m0 + ar) * K;
    const size_t brow = (size_t)(n0 + br) * K;

    {
        #pragma unroll
        for (int g = 0; g < 2; ++g) {
            int slot = aq * 2 + g;
            uint32_t off = (uint32_t)ar * 128 + (((uint32_t)slot * 16) ^ aswz);
            cp16(smem_base + SM_AH + off, Ah_ + arow + slot * 8);
            cp16(smem_base + SM_AL + off, Al_ + arow + slot * 8);
        }
        #pragma unroll
        for (int g = 0; g < 4; ++g) {
            int slot = bq2 * 4 + g;
            uint32_t off = (uint32_t)br * 128 + (((uint32_t)slot * 16) ^ bswz);
            cp16(smem_base + SM_BH + off, Bh_ + brow + slot * 8);
            cp16(smem_base + SM_BL + off, Bl_ + brow + slot * 8);
        }
        cp_commit();
    }

    for (int c = 0; c < nchunks; ++c) {
        if (c + 1 < nchunks) {
            const int kc = (c + 1) << 6;
            const uint32_t sb = smem_base + ((c + 1) & 1) * SM_STAGE;
            #pragma unroll
            for (int g = 0; g < 2; ++g) {
                int slot = aq * 2 + g;
                uint32_t off = (uint32_t)ar * 128 + (((uint32_t)slot * 16) ^ aswz);
                cp16(sb + SM_AH + off, Ah_ + arow + kc + slot * 8);
                cp16(sb + SM_AL + off, Al_ + arow + kc + slot * 8);
            }
            #pragma unroll
            for (int g = 0; g < 4; ++g) {
                int slot = bq2 * 4 + g;
                uint32_t off = (uint32_t)br * 128 + (((uint32_t)slot * 16) ^ bswz);
                cp16(sb + SM_BH + off, Bh_ + brow + kc + slot * 8);
                cp16(sb + SM_BL + off, Bl_ + brow + kc + slot * 8);
            }
            cp_commit();
            cp_wait1();
        } else {
            cp_wait0();
        }
        __syncthreads();
        const uint32_t sb = smem_base + (c & 1) * SM_STAGE;
        #pragma unroll
        for (int ks = 0; ks < 4; ++ks) {
            const uint32_t kb = (uint32_t)(ks * 32 + kqoff);
            uint32_t ah[2][4], al[2][4], bh[4][2], bl[4][2];
            #pragma unroll
            for (int i = 0; i < 2; ++i) {
                uint32_t row = (uint32_t)(rowA0 + i * 16);
                uint32_t off = row * 128 + (kb ^ ((row & 7) << 4));
                ldsm4(sb + SM_AH + off, ah[i]);
                ldsm4(sb + SM_AL + off, al[i]);
            }
            #pragma unroll
            for (int j2 = 0; j2 < 2; ++j2) {
                uint32_t row = (uint32_t)(wn + j2 * 16 + (q & 1) * 8 + rin);
                uint32_t off = row * 128 + (kb ^ ((row & 7) << 4));
                uint32_t r4v[4];
                ldsm4(sb + SM_BH + off, r4v);
                bh[2*j2][0] = r4v[0]; bh[2*j2][1] = r4v[2];
                bh[2*j2+1][0] = r4v[1]; bh[2*j2+1][1] = r4v[3];
                ldsm4(sb + SM_BL + off, r4v);
                bl[2*j2][0] = r4v[0]; bl[2*j2][1] = r4v[2];
                bl[2*j2+1][0] = r4v[1]; bl[2*j2+1][1] = r4v[3];
            }
            #pragma unroll
            for (int i = 0; i < 2; ++i)
                #pragma unroll
                for (int j = 0; j < 4; ++j) {
                    mma_bf16(acc[i][j], ah[i], bh[j][0], bh[j][1]);
                    mma_bf16(acc[i][j], ah[i], bl[j][0], bl[j][1]);
                    mma_bf16(acc[i][j], al[i], bh[j][0], bh[j][1]);
                }
        }
        __syncthreads();
    }

    if (flags & FL_QKV) {
        __nv_bfloat16 *dsth, *dstl;
        float scale;
        if (n0 == 0)        { dsth = g_qh; dstl = g_ql; scale = 0.36067376022224085f; }  // 0.25*log2(e)
        else if (n0 == 128) { dsth = g_kh; dstl = g_kl; scale = 1.f; }
        else                { dsth = g_vh; dstl = nullptr; scale = 1.f; }                 // V: single bf16
        #pragma unroll
        for (int i = 0; i < 2; ++i)
            #pragma unroll
            for (int j = 0; j < 4; ++j) {
                int cp = wn + j * 8 + (lane & 3) * 2;
                float b0 = sBias[cp], b1 = sBias[cp + 1];
                int hh8 = (cp >> 4) & 7, e = cp & 15;
                #pragma unroll
                for (int rr = 0; rr < 2; ++rr) {
                    int r = m0 + wm + i * 16 + (lane >> 2) + rr * 8;
                    float v0 = (acc[i][j][rr * 2 + 0] + b0) * scale;
                    float v1 = (acc[i][j][rr * 2 + 1] + b1) * scale;
                    int bb = r >> 10, t = r & 1023;
                    int bh128 = bb * 8 + hh8;
                    size_t idx = ((size_t)bh128 * 1024 + t) * 16 + e;
                    if (dstl) {
                        uint32_t hh, ll;
                        split2(v0, v1, hh, ll);
                        *(uint32_t*)(dsth + idx) = hh;
                        *(uint32_t*)(dstl + idx) = ll;
                    } else {
                        *(uint32_t*)(dsth + idx) = pack2(v0, v1);
                    }
                }
            }
    } else if (!(flags & FL_LN)) {
        #pragma unroll
        for (int i = 0; i < 2; ++i)
            #pragma unroll
            for (int j = 0; j < 4; ++j) {
                int cp = wn + j * 8 + (lane & 3) * 2;
                float b0 = sBias[cp], b1 = sBias[cp + 1];
                int r0 = m0 + wm + i * 16 + (lane >> 2);
                float v0 = acc[i][j][0] + b0, v1 = acc[i][j][1] + b1;
                float v2 = acc[i][j][2] + b0, v3 = acc[i][j][3] + b1;
                if (flags & FL_GELU) { v0 = gelu_f(v0); v1 = gelu_f(v1); v2 = gelu_f(v2); v3 = gelu_f(v3); }
                if (flags & FL_F32) {
                    *(float2*)(Cf + (size_t)r0 * ldc + n0 + cp)       = make_float2(v0, v1);
                    *(float2*)(Cf + (size_t)(r0 + 8) * ldc + n0 + cp) = make_float2(v2, v3);
                }
                if (flags & FL_BF) {
                    uint32_t hh, ll;
                    split2(v0, v1, hh, ll);
                    *(uint32_t*)(Cbh + (size_t)r0 * ldc + n0 + cp) = hh;
                    *(uint32_t*)(Cbl + (size_t)r0 * ldc + n0 + cp) = ll;
                    split2(v2, v3, hh, ll);
                    *(uint32_t*)(Cbh + (size_t)(r0 + 8) * ldc + n0 + cp) = hh;
                    *(uint32_t*)(Cbl + (size_t)(r0 + 8) * ldc + n0 + cp) = ll;
                }
            }
    } else {
        #pragma unroll
        for (int i = 0; i < 2; ++i)
            #pragma unroll
            for (int j = 0; j < 4; ++j) {
                int cp = wn + j * 8 + (lane & 3) * 2;
                float b0 = sBias[cp], b1 = sBias[cp + 1];
                int r0 = wm + i * 16 + (lane >> 2);
                Cs[r0 * 132 + cp]           = acc[i][j][0] + b0;
                Cs[r0 * 132 + cp + 1]       = acc[i][j][1] + b1;
                Cs[(r0 + 8) * 132 + cp]     = acc[i][j][2] + b0;
                Cs[(r0 + 8) * 132 + cp + 1] = acc[i][j][3] + b1;
            }
        __syncthreads();
        for (int rr = 0; rr < 8; ++rr) {
            int row = wid * 8 + rr;
            const float* cr = Cs + row * 132 + lane * 4;
            float2 p0 = *(const float2*)(cr);
            float2 p1 = *(const float2*)(cr + 2);
            const float4 rv = *(const float4*)(resid + (size_t)(m0 + row) * 128 + lane * 4);
            float v0 = p0.x + rv.x, v1 = p0.y + rv.y, v2 = p1.x + rv.z, v3 = p1.y + rv.w;
            float s  = v0 + v1 + v2 + v3;
            float sq2 = v0 * v0 + v1 * v1 + v2 * v2 + v3 * v3;
            #pragma unroll
            for (int off = 16; off > 0; off >>= 1) {
                s   += __shfl_xor_sync(0xffffffffu, s,   off);
                sq2 += __shfl_xor_sync(0xffffffffu, sq2, off);
            }
            float mean = s * (1.f / 128.f);
            float var  = sq2 * (1.f / 128.f) - mean * mean;
            float is   = rsqrtf(var + 1e-5f);
            int cb = lane * 4;
            float o0 = (v0 - mean) * is * sG[cb]     + sBe[cb];
            float o1 = (v1 - mean) * is * sG[cb + 1] + sBe[cb + 1];
            float o2 = (v2 - mean) * is * sG[cb + 2] + sBe[cb + 2];
            float o3 = (v3 - mean) * is * sG[cb + 3] + sBe[cb + 3];
            size_t base = (size_t)(m0 + row) * 128 + cb;
            if (flags & FL_F32)
                *(float4*)(Cf + base) = make_float4(o0, o1, o2, o3);
            if (flags & FL_BF) {
                uint32_t hh, ll;
                split2(o0, o1, hh, ll);
                *(uint32_t*)(Cbh + base) = hh; *(uint32_t*)(Cbl + base) = ll;
                split2(o2, o3, hh, ll);
                *(uint32_t*)(Cbh + base + 2) = hh; *(uint32_t*)(Cbl + base + 2) = ll;
            }
        }
    }
}

// ---------------------------------------------------------------------------
// Flash-style causal attention via HMMA, DIAGONAL-BALANCED, 8 warps/CTA,
// cp.async double-buffered K/V staging. ex2-domain softmax (Q pre-scaled).
// P and V plain bf16 (normalization/averaging cancels rounding); P@V = 1 mma/nt.
// Q@K stays 3-mma exact.
// ---------------------------------------------------------------------------
struct TileAcc {
    float o[2][4];
    float lsum[2];
};

__device__ __forceinline__ void attn_step(
    const uint32_t* aqh, const uint32_t* aql,
    const uint32_t* kfh, const uint32_t* kfl,
    int kbase, int W, int r4, int c2,
    const uint32_t* vbh,
    TileAcc& T)
{
    float s[2][4];
    #pragma unroll
    for (int jj = 0; jj < 2; ++jj)
        #pragma unroll
        for (int e = 0; e < 4; ++e) s[jj][e] = 0.f;
    #pragma unroll
    for (int jj = 0; jj < 2; ++jj) {
        uint32_t kb0 = kfh[jj], kb1 = kfh[2 + jj];
        uint32_t kl0 = kfl[jj], kl1 = kfl[2 + jj];
        mma_bf16(s[jj], aqh, kb0, kb1);
        mma_bf16(s[jj], aqh, kl0, kl1);
        mma_bf16(s[jj], aql, kb0, kb1);
    }
    uint32_t pa[4];
    const bool full = (kbase + 15 <= W);
    const int t0 = W + r4, t1 = t0 + 8;
    #pragma unroll
    for (int jj = 0; jj < 2; ++jj) {
        int ub = kbase + jj * 8 + c2;
        float p0 = ex2f(s[jj][0]);
        float p1 = ex2f(s[jj][1]);
        float p2 = ex2f(s[jj][2]);
        float p3 = ex2f(s[jj][3]);
        if (!full) {
            if (ub > t0)     p0 = 0.f;
            if (ub + 1 > t0) p1 = 0.f;
            if (ub > t1)     p2 = 0.f;
            if (ub + 1 > t1) p3 = 0.f;
        }
        T.lsum[0] += p0 + p1;
        T.lsum[1] += p2 + p3;
        pa[jj * 2 + 0] = pack2(p0, p1);
        pa[jj * 2 + 1] = pack2(p2, p3);
    }
    #pragma unroll
    for (int nt = 0; nt < 2; ++nt)
        mma_bf16(T.o[nt], pa, vbh[nt * 2], vbh[nt * 2 + 1]);
}

__global__ __launch_bounds__(256)
void attn_mma(const __nv_bfloat16* __restrict__ Qh, const __nv_bfloat16* __restrict__ Ql,
              const __nv_bfloat16* __restrict__ Kh, const __nv_bfloat16* __restrict__ Kl,
              const __nv_bfloat16* __restrict__ Vh,
              __nv_bfloat16* __restrict__ Oh, __nv_bfloat16* __restrict__ Ol)
{
    __shared__ __align__(16) __nv_bfloat16 sKh[2][128 * 24], sKl[2][128 * 24];
    __shared__ __align__(16) __nv_bfloat16 sVh[2][128 * 24];

    const int pa_ = blockIdx.x;
    const int bh = blockIdx.y;
    const int a = pa_, bqt = 15 - pa_;
    const int tid = threadIdx.x;
    const int w = tid >> 5, lane = tid & 31;
    const int wg = w >> 2, wi = w & 3;
    const int myqt = wg ? bqt : a;
    const int W = myqt * 64 + wi * 16;
    const int r4 = lane >> 2, c2 = (lane & 3) * 2;
    const uint32_t skh0 = smem_u32(sKh[0]), skl0 = smem_u32(sKl[0]);
    const uint32_t skh1 = smem_u32(sKh[1]), skl1 = smem_u32(sKl[1]);
    const uint32_t svh0 = smem_u32(sVh[0]), svh1 = smem_u32(sVh[1]);

    const int mi = lane >> 3, li = lane & 7;
    const uint32_t vfrag_off = (uint32_t)(((li + (mi & 1) * 8) * 24 + (mi >> 1) * 8) * 2);
    const uint32_t kfrag_off = (uint32_t)(((mi & 1) * 8 + li) * 48 + (mi >> 1) * 16);

    if (tid < 128) {
        int qrow = (tid < 64) ? (a * 64 + tid) : (bqt * 64 + tid - 64);
        const __nv_bfloat16* srcH = Qh + ((size_t)bh * 1024 + qrow) * 16;
        const __nv_bfloat16* srcL = Ql + ((size_t)bh * 1024 + qrow) * 16;
        *(uint4*)&sKh[0][tid * 24]     = ((const uint4*)srcH)[0];
        *(uint4*)&sKh[0][tid * 24 + 8] = ((const uint4*)srcH)[1];
        *(uint4*)&sKl[0][tid * 24]     = ((const uint4*)srcL)[0];
        *(uint4*)&sKl[0][tid * 24 + 8] = ((const uint4*)srcL)[1];
    }
    __syncthreads();

    uint32_t aqh[4], aql[4];
    {
        uint32_t row = (uint32_t)(wg * 64 + wi * 16 + (mi & 1) * 8 + li);
        uint32_t boff = row * 48 + (uint32_t)(mi >> 1) * 16;
        ldsm4(skh0 + boff, aqh);
        ldsm4(skl0 + boff, aql);
    }
    __syncthreads();

    TileAcc T;
    #pragma unroll
    for (int nt = 0; nt < 2; ++nt)
        #pragma unroll
        for (int e = 0; e < 4; ++e) T.o[nt][e] = 0.f;
    T.lsum[0] = T.lsum[1] = 0.f;

    const int strow = tid >> 1, sthalf = tid & 1;
    const uint32_t stoff = (uint32_t)strow * 48 + (uint32_t)sthalf * 16;
    const size_t stg_base = ((size_t)bh * 1024 + strow) * 16 + sthalf * 8;

    const int ntiles = (bqt + 2) >> 1;
    {
        const size_t goff = stg_base;
        cp16(skh0 + stoff, Kh + goff);
        cp16(skl0 + stoff, Kl + goff);
        cp16(svh0 + stoff, Vh + goff);
        cp_commit();
    }

    for (int tile = 0; tile < ntiles; ++tile) {
        if (tile + 1 < ntiles) {
            const size_t goff = stg_base + (size_t)((tile + 1) << 7) * 16;
            const uint32_t kh = ((tile + 1) & 1) ? skh1 : skh0;
            const uint32_t kl = ((tile + 1) & 1) ? skl1 : skl0;
            const uint32_t vh = ((tile + 1) & 1) ? svh1 : svh0;
            cp16(kh + stoff, Kh + goff);
            cp16(kl + stoff, Kl + goff);
            cp16(vh + stoff, Vh + goff);
            cp_commit();
            cp_wait1();
        } else {
            cp_wait0();
        }
        __syncthreads();
        const int bi = tile & 1;
        const uint32_t ckh = bi ? skh1 : skh0;
        const uint32_t ckl = bi ? skl1 : skl0;
        const uint32_t cvh = bi ? svh1 : svh0;
        const int u0 = tile << 7;

        if (u0 <= W + 15) {
            #pragma unroll
            for (int kk = 0; kk < 8; ++kk) {
                const int kbase = u0 + kk * 16;
                if (kbase > W + 15) break;
                uint32_t vbh[4], kfh[4], kfl[4];
                uint32_t tileoff = (uint32_t)(kk * 16 * 48);
                ldsm4t(cvh + vfrag_off + tileoff, vbh);
                ldsm4(ckh + kfrag_off + tileoff, kfh);
                ldsm4(ckl + kfrag_off + tileoff, kfl);
                attn_step(aqh, aql, kfh, kfl, kbase, W, r4, c2, vbh, T);
            }
        }
        __syncthreads();
    }

    const int b = bh >> 3, h = bh & 7;
    const int bT = b << 10;
    {
        float l0 = T.lsum[0], l1 = T.lsum[1];
        l0 += __shfl_xor_sync(0xffffffffu, l0, 1);
        l0 += __shfl_xor_sync(0xffffffffu, l0, 2);
        l1 += __shfl_xor_sync(0xffffffffu, l1, 1);
        l1 += __shfl_xor_sync(0xffffffffu, l1, 2);
        float i0 = 1.f / l0, i1 = 1.f / l1;
        int row0 = bT + W + r4;
        #pragma unroll
        for (int nt = 0; nt < 2; ++nt) {
            int col = (h << 4) + nt * 8 + c2;
            uint32_t hh, ll;
            split2(T.o[nt][0] * i0, T.o[nt][1] * i0, hh, ll);
            *(uint32_t*)(Oh + (size_t)row0 * 128 + col) = hh;
            *(uint32_t*)(Ol + (size_t)row0 * 128 + col) = ll;
            split2(T.o[nt][2] * i1, T.o[nt][3] * i1, hh, ll);
            *(uint32_t*)(Oh + (size_t)(row0 + 8) * 128 + col) = hh;
            *(uint32_t*)(Ol + (size_t)(row0 + 8) * 128 + col) = ll;
        }
    }
}

// ---------------------------------------------------------------------------
extern "C" void kernel_launch(void* const* d_in, const int* in_sizes, int n_in,
                              void* d_out, int out_size)
{
    const float* x   = (const float*)d_in[0];
    const float* Wq  = (const float*)d_in[1];
    const float* bq  = (const float*)d_in[2];
    const float* Wk  = (const float*)d_in[3];
    const float* bk  = (const float*)d_in[4];
    const float* Wv  = (const float*)d_in[5];
    const float* bv  = (const float*)d_in[6];
    const float* Wp  = (const float*)d_in[7];
    const float* bp  = (const float*)d_in[8];
    const float* W1  = (const float*)d_in[9];
    const float* b1  = (const float*)d_in[10];
    const float* W2  = (const float*)d_in[11];
    const float* b2  = (const float*)d_in[12];
    const float* g1  = (const float*)d_in[13];
    const float* be1 = (const float*)d_in[14];
    const float* g2  = (const float*)d_in[15];
    const float* be2 = (const float*)d_in[16];
    float* out = (float*)d_out;

    float *p_x1, *p_bqkv;
    __nv_bfloat16 *p_xh, *p_xl, *p_qh, *p_ql, *p_kh, *p_kl, *p_vh;
    __nv_bfloat16 *p_ath, *p_atl, *p_x1h, *p_x1l, *p_hih, *p_hil;
    __nv_bfloat16 *p_wqh, *p_wql, *p_wph, *p_wpl, *p_w1h, *p_w1l, *p_w2h, *p_w2l;
    cudaGetSymbolAddress((void**)&p_x1,  g_x1);
    cudaGetSymbolAddress((void**)&p_bqkv, g_bqkv);
    cudaGetSymbolAddress((void**)&p_xh,  g_xh);   cudaGetSymbolAddress((void**)&p_xl,  g_xl);
    cudaGetSymbolAddress((void**)&p_qh,  g_qh);   cudaGetSymbolAddress((void**)&p_ql,  g_ql);
    cudaGetSymbolAddress((void**)&p_kh,  g_kh);   cudaGetSymbolAddress((void**)&p_kl,  g_kl);
    cudaGetSymbolAddress((void**)&p_vh,  g_vh);
    cudaGetSymbolAddress((void**)&p_ath, g_ath);  cudaGetSymbolAddress((void**)&p_atl, g_atl);
    cudaGetSymbolAddress((void**)&p_x1h, g_x1h);  cudaGetSymbolAddress((void**)&p_x1l, g_x1l);
    cudaGetSymbolAddress((void**)&p_hih, g_hih);  cudaGetSymbolAddress((void**)&p_hil, g_hil);
    cudaGetSymbolAddress((void**)&p_wqh, g_wqkv_h); cudaGetSymbolAddress((void**)&p_wql, g_wqkv_l);
    cudaGetSymbolAddress((void**)&p_wph, g_wp_h);   cudaGetSymbolAddress((void**)&p_wpl, g_wp_l);
    cudaGetSymbolAddress((void**)&p_w1h, g_w1_h);   cudaGetSymbolAddress((void**)&p_w1l, g_w1_l);
    cudaGetSymbolAddress((void**)&p_w2h, g_w2_h);   cudaGetSymbolAddress((void**)&p_w2l, g_w2_l);

    cudaFuncSetAttribute(gemm_mma, cudaFuncAttributeMaxDynamicSharedMemorySize, SM_TOTAL);

    // 1. pack weights + split input activations
    pack_kernel<<<256, 256>>>(Wq, bq, Wk, bk, Wv, bv, Wp, W1, W2);
    split_x_kernel<<<BT_TOTAL * DMODEL / 4 / 256, 256>>>(x, p_xh, p_xl);
    // 2. QKV -> bf16 head-major (q pre-scaled by 0.25*log2e; v single bf16)
    gemm_mma<<<dim3(256, 3), 256, SM_TOTAL>>>(p_xh, p_xl, 128, p_wqh, p_wql,
                                              p_bqkv, nullptr, nullptr, nullptr,
                                              nullptr, nullptr, nullptr, NQKV, FL_QKV);
    // 3. causal attention (diagonal-balanced) -> bf16 hi/lo
    attn_mma<<<dim3(8, 128), 256>>>(p_qh, p_ql, p_kh, p_kl, p_vh, p_ath, p_atl);
    // 4. proj + bias + resid + LN1 -> fp32 x1 + bf16 hi/lo
    gemm_mma<<<dim3(256, 1), 256, SM_TOTAL>>>(p_ath, p_atl, 128, p_wph, p_wpl,
                                              bp, x, g1, be1,
                                              p_x1, p_x1h, p_x1l, DMODEL, FL_LN | FL_F32 | FL_BF);
    // 5. MLP up + GELU -> bf16 hi/lo
    gemm_mma<<<dim3(256, 4), 256, SM_TOTAL>>>(p_x1h, p_x1l, 128, p_w1h, p_w1l,
                                              b1, nullptr, nullptr, nullptr,
                                              nullptr, p_hih, p_hil, FFDIM, FL_GELU | FL_BF);
    // 6. MLP down (K=512) + bias + resid + LN2 -> out
    gemm_mma<<<dim3(256, 1), 256, SM_TOTAL>>>(p_hih, p_hil, 512, p_w2h, p_w2l,
                                              b2, p_x1, g2, be2,
                                              out, nullptr, nullptr, DMODEL, FL_LN | FL_F32);
}

// round 15
// speedup vs baseline: 1.1991x; 1.0781x over previous
#include <cuda_runtime.h>
#include <cuda_bf16.h>
#include <cstdint>
#include <math.h>

// Block_36455682408804: transformer block  B=16 T=1024 D=128 H=8 HS=16 FF=512
#define BT_TOTAL 16384
#define DMODEL   128
#define FFDIM    512
#define NQKV     384

// ---------------------------------------------------------------------------
// device-global scratch (allocation-free, graph-capturable)
// ---------------------------------------------------------------------------
__device__ float g_x1 [BT_TOTAL * DMODEL];                // fp32 residual for MLP2
__device__ float g_bqkv[NQKV];
__device__ __nv_bfloat16 g_xh [BT_TOTAL * DMODEL], g_xl [BT_TOTAL * DMODEL];
__device__ __nv_bfloat16 g_qh [128 * 1024 * 16],   g_ql [128 * 1024 * 16];   // [bh][t][16], pre-scaled 0.25*log2e
__device__ __nv_bfloat16 g_kh [128 * 1024 * 16];                              // [bh][t][16] single bf16
__device__ __nv_bfloat16 g_vh [128 * 1024 * 16];                              // [bh][t][16] single bf16
__device__ __nv_bfloat16 g_ath[BT_TOTAL * DMODEL], g_atl[BT_TOTAL * DMODEL];
__device__ __nv_bfloat16 g_x1h[BT_TOTAL * DMODEL], g_x1l[BT_TOTAL * DMODEL];
__device__ __nv_bfloat16 g_hih[BT_TOTAL * FFDIM],  g_hil[BT_TOTAL * FFDIM];
__device__ __nv_bfloat16 g_wqkv_h[NQKV * DMODEL],  g_wqkv_l[NQKV * DMODEL];
__device__ __nv_bfloat16 g_wp_h[DMODEL * DMODEL],  g_wp_l[DMODEL * DMODEL];
__device__ __nv_bfloat16 g_w1_h[FFDIM * DMODEL],   g_w1_l[FFDIM * DMODEL];
__device__ __nv_bfloat16 g_w2_h[DMODEL * FFDIM],   g_w2_l[DMODEL * FFDIM];

// ---------------------------------------------------------------------------
// helpers
// ---------------------------------------------------------------------------
__device__ __forceinline__ void split_bf(float v, __nv_bfloat16& h, __nv_bfloat16& l) {
    h = __float2bfloat16(v);
    l = __float2bfloat16(v - __bfloat162float(h));
}
__device__ __forceinline__ void split2(float x, float y, uint32_t& h, uint32_t& l) {
    asm("cvt.rn.bf16x2.f32 %0, %1, %2;" : "=r"(h) : "f"(y), "f"(x));
    float xh = __uint_as_float(h << 16);
    float yh = __uint_as_float(h & 0xffff0000u);
    float xl = x - xh, yl = y - yh;
    asm("cvt.rn.bf16x2.f32 %0, %1, %2;" : "=r"(l) : "f"(yl), "f"(xl));
}
__device__ __forceinline__ uint32_t pack2(float x, float y) {
    uint32_t r;
    asm("cvt.rn.bf16x2.f32 %0, %1, %2;" : "=r"(r) : "f"(y), "f"(x));
    return r;
}
__device__ __forceinline__ float ex2f(float x) {
    float r; asm("ex2.approx.f32 %0, %1;" : "=f"(r) : "f"(x)); return r;
}
__device__ __forceinline__ uint32_t smem_u32(const void* p) {
    uint32_t a;
    asm("{ .reg .u64 t; cvta.to.shared.u64 t, %1; cvt.u32.u64 %0, t; }" : "=r"(a) : "l"(p));
    return a;
}
__device__ __forceinline__ void ldsm4(uint32_t addr, uint32_t* r) {
    asm volatile("ldmatrix.sync.aligned.m8n8.x4.shared.b16 {%0,%1,%2,%3}, [%4];"
                 : "=r"(r[0]), "=r"(r[1]), "=r"(r[2]), "=r"(r[3]) : "r"(addr));
}
__device__ __forceinline__ void ldsm4t(uint32_t addr, uint32_t* r) {
    asm volatile("ldmatrix.sync.aligned.m8n8.x4.trans.shared.b16 {%0,%1,%2,%3}, [%4];"
                 : "=r"(r[0]), "=r"(r[1]), "=r"(r[2]), "=r"(r[3]) : "r"(addr));
}
__device__ __forceinline__ void mma_bf16(float* d, const uint32_t* a, uint32_t b0, uint32_t b1) {
    asm volatile("mma.sync.aligned.m16n8k16.row.col.f32.bf16.bf16.f32 "
                 "{%0,%1,%2,%3}, {%4,%5,%6,%7}, {%8,%9}, {%0,%1,%2,%3};"
                 : "+f"(d[0]), "+f"(d[1]), "+f"(d[2]), "+f"(d[3])
                 : "r"(a[0]), "r"(a[1]), "r"(a[2]), "r"(a[3]), "r"(b0), "r"(b1));
}
__device__ __forceinline__ void cp16(uint32_t saddr, const void* gptr) {
    asm volatile("cp.async.cg.shared.global [%0], [%1], 16;" :: "r"(saddr), "l"(gptr));
}
__device__ __forceinline__ void cp_commit() { asm volatile("cp.async.commit_group;"); }
__device__ __forceinline__ void cp_wait0() { asm volatile("cp.async.wait_group 0;"); }
__device__ __forceinline__ void cp_wait1() { asm volatile("cp.async.wait_group 1;"); }
__device__ __forceinline__ float gelu_f(float v) {
    return 0.5f * v * (1.f + erff(v * 0.7071067811865475f));
}

// ---------------------------------------------------------------------------
// pack weights: transpose to [N,K], split bf16 hi/lo
// ---------------------------------------------------------------------------
__global__ void pack_kernel(const float* __restrict__ Wq, const float* __restrict__ bq,
                            const float* __restrict__ Wk, const float* __restrict__ bk,
                            const float* __restrict__ Wv, const float* __restrict__ bv,
                            const float* __restrict__ Wp, const float* __restrict__ W1,
                            const float* __restrict__ W2)
{
    int i0 = blockIdx.x * blockDim.x + threadIdx.x;
    int stride = gridDim.x * blockDim.x;
    for (int i = i0; i < NQKV * DMODEL; i += stride) {
        int n = i >> 7, k = i & 127;
        float v;
        if (n < 128)      v = Wq[((n >> 4) << 11) + k * 16 + (n & 15)];
        else if (n < 256) { int m = n - 128; v = Wk[((m >> 4) << 11) + k * 16 + (m & 15)]; }
        else              { int m = n - 256; v = Wv[((m >> 4) << 11) + k * 16 + (m & 15)]; }
        split_bf(v, g_wqkv_h[i], g_wqkv_l[i]);
    }
    for (int i = i0; i < DMODEL * DMODEL; i += stride) {
        int n = i >> 7, k = i & 127;
        split_bf(Wp[k * 128 + n], g_wp_h[i], g_wp_l[i]);
    }
    for (int i = i0; i < FFDIM * DMODEL; i += stride) {
        int n = i >> 7, k = i & 127;
        split_bf(W1[k * 512 + n], g_w1_h[i], g_w1_l[i]);
    }
    for (int i = i0; i < DMODEL * FFDIM; i += stride) {
        int n = i >> 9, k = i & 511;
        split_bf(W2[k * 128 + n], g_w2_h[i], g_w2_l[i]);
    }
    for (int i = i0; i < NQKV; i += stride)
        g_bqkv[i] = (i < 128) ? bq[i] : (i < 256 ? bk[i - 128] : bv[i - 256]);
}

// split activations x -> xh, xl
__global__ void split_x_kernel(const float* __restrict__ X,
                               __nv_bfloat16* __restrict__ Xh, __nv_bfloat16* __restrict__ Xl)
{
    int i = blockIdx.x * blockDim.x + threadIdx.x;
    float4 v = ((const float4*)X)[i];
    uint32_t h0, l0, h1, l1;
    split2(v.x, v.y, h0, l0); split2(v.z, v.w, h1, l1);
    ((uint2*)Xh)[i] = make_uint2(h0, h1);
    ((uint2*)Xl)[i] = make_uint2(l0, l1);
}

// ---------------------------------------------------------------------------
// HMMA GEMM, all-bf16 inputs, cp.async 2-stage pipeline, 256 threads.
// CTA tile 64x128 (M x N), 8 warps (2m x 4n), warp tile 32x32, K chunk 64.
// flags: 1=gelu, 2=LN(+resid), 4=write fp32, 8=write bf16 hi/lo, 16=QKV layout
// ---------------------------------------------------------------------------
#define FL_GELU 1
#define FL_LN   2
#define FL_F32  4
#define FL_BF   8
#define FL_QKV  16

#define SM_AH 0
#define SM_AL 8192
#define SM_BH 16384
#define SM_BL 32768
#define SM_STAGE 49152
#define SM_CS 0
#define SM_BIAS 98304
#define SM_G    98816
#define SM_BE   99328
#define SM_TOTAL 99840

__global__ __launch_bounds__(256, 2)
void gemm_mma(const __nv_bfloat16* __restrict__ Ah_, const __nv_bfloat16* __restrict__ Al_,
              int K,
              const __nv_bfloat16* __restrict__ Bh_, const __nv_bfloat16* __restrict__ Bl_,
              const float* __restrict__ bias, const float* __restrict__ resid,
              const float* __restrict__ gamma, const float* __restrict__ beta,
              float* __restrict__ Cf, __nv_bfloat16* __restrict__ Cbh, __nv_bfloat16* __restrict__ Cbl,
              int ldc, int flags)
{
    extern __shared__ unsigned char smraw[];
    const uint32_t smem_base = smem_u32(smraw);
    float* sBias = (float*)(smraw + SM_BIAS);
    float* sG    = (float*)(smraw + SM_G);
    float* sBe   = (float*)(smraw + SM_BE);
    float* Cs    = (float*)(smraw + SM_CS);

    const int tid = threadIdx.x;
    const int wid = tid >> 5, lane = tid & 31;
    const int m0 = blockIdx.x * 64, n0 = blockIdx.y * 128;
    const int wm = (wid & 1) * 32, wn = (wid >> 1) * 32;

    if (tid < 128) {
        sBias[tid] = bias[n0 + tid];
        if (flags & FL_LN) { sG[tid] = gamma[tid]; sBe[tid] = beta[tid]; }
    }

    const int q = lane >> 3, rin = lane & 7;
    const int rowA0 = wm + (q & 1) * 8 + rin;
    const int kqoff = (q >> 1) * 16;

    const int ar = tid >> 2, aq = tid & 3;
    const int br = tid >> 1, bq2 = tid & 1;
    const uint32_t aswz = (uint32_t)(ar & 7) << 4;
    const uint32_t bswz = (uint32_t)(br & 7) << 4;

    float acc[2][4][4];
    #pragma unroll
    for (int i = 0; i < 2; ++i)
        #pragma unroll
        for (int j = 0; j < 4; ++j)
            #pragma unroll
            for (int e = 0; e < 4; ++e) acc[i][j][e] = 0.f;

    const int nchunks = K >> 6;
    const size_t arow = (size_t)(m0 + ar) * K;
    const size_t brow = (size_t)(n0 + br) * K;

    {
        #pragma unroll
        for (int g = 0; g < 2; ++g) {
            int slot = aq * 2 + g;
            uint32_t off = (uint32_t)ar * 128 + (((uint32_t)slot * 16) ^ aswz);
            cp16(smem_base + SM_AH + off, Ah_ + arow + slot * 8);
            cp16(smem_base + SM_AL + off, Al_ + arow + slot * 8);
        }
        #pragma unroll
        for (int g = 0; g < 4; ++g) {
            int slot = bq2 * 4 + g;
            uint32_t off = (uint32_t)br * 128 + (((uint32_t)slot * 16) ^ bswz);
            cp16(smem_base + SM_BH + off, Bh_ + brow + slot * 8);
            cp16(smem_base + SM_BL + off, Bl_ + brow + slot * 8);
        }
        cp_commit();
    }

    for (int c = 0; c < nchunks; ++c) {
        if (c + 1 < nchunks) {
            const int kc = (c + 1) << 6;
            const uint32_t sb = smem_base + ((c + 1) & 1) * SM_STAGE;
            #pragma unroll
            for (int g = 0; g < 2; ++g) {
                int slot = aq * 2 + g;
                uint32_t off = (uint32_t)ar * 128 + (((uint32_t)slot * 16) ^ aswz);
                cp16(sb + SM_AH + off, Ah_ + arow + kc + slot * 8);
                cp16(sb + SM_AL + off, Al_ + arow + kc + slot * 8);
            }
            #pragma unroll
            for (int g = 0; g < 4; ++g) {
                int slot = bq2 * 4 + g;
                uint32_t off = (uint32_t)br * 128 + (((uint32_t)slot * 16) ^ bswz);
                cp16(sb + SM_BH + off, Bh_ + brow + kc + slot * 8);
                cp16(sb + SM_BL + off, Bl_ + brow + kc + slot * 8);
            }
            cp_commit();
            cp_wait1();
        } else {
            cp_wait0();
        }
        __syncthreads();
        const uint32_t sb = smem_base + (c & 1) * SM_STAGE;
        #pragma unroll
        for (int ks = 0; ks < 4; ++ks) {
            const uint32_t kb = (uint32_t)(ks * 32 + kqoff);
            uint32_t ah[2][4], al[2][4], bh[4][2], bl[4][2];
            #pragma unroll
            for (int i = 0; i < 2; ++i) {
                uint32_t row = (uint32_t)(rowA0 + i * 16);
                uint32_t off = row * 128 + (kb ^ ((row & 7) << 4));
                ldsm4(sb + SM_AH + off, ah[i]);
                ldsm4(sb + SM_AL + off, al[i]);
            }
            #pragma unroll
            for (int j2 = 0; j2 < 2; ++j2) {
                uint32_t row = (uint32_t)(wn + j2 * 16 + (q & 1) * 8 + rin);
                uint32_t off = row * 128 + (kb ^ ((row & 7) << 4));
                uint32_t r4v[4];
                ldsm4(sb + SM_BH + off, r4v);
                bh[2*j2][0] = r4v[0]; bh[2*j2][1] = r4v[2];
                bh[2*j2+1][0] = r4v[1]; bh[2*j2+1][1] = r4v[3];
                ldsm4(sb + SM_BL + off, r4v);
                bl[2*j2][0] = r4v[0]; bl[2*j2][1] = r4v[2];
                bl[2*j2+1][0] = r4v[1]; bl[2*j2+1][1] = r4v[3];
            }
            #pragma unroll
            for (int i = 0; i < 2; ++i)
                #pragma unroll
                for (int j = 0; j < 4; ++j) {
                    mma_bf16(acc[i][j], ah[i], bh[j][0], bh[j][1]);
                    mma_bf16(acc[i][j], ah[i], bl[j][0], bl[j][1]);
                    mma_bf16(acc[i][j], al[i], bh[j][0], bh[j][1]);
                }
        }
        __syncthreads();
    }

    if (flags & FL_QKV) {
        __nv_bfloat16 *dsth, *dstl;
        float scale;
        if (n0 == 0)        { dsth = g_qh; dstl = g_ql; scale = 0.36067376022224085f; }  // 0.25*log2(e)
        else if (n0 == 128) { dsth = g_kh; dstl = nullptr; scale = 1.f; }                // K: single bf16
        else                { dsth = g_vh; dstl = nullptr; scale = 1.f; }                // V: single bf16
        #pragma unroll
        for (int i = 0; i < 2; ++i)
            #pragma unroll
            for (int j = 0; j < 4; ++j) {
                int cp = wn + j * 8 + (lane & 3) * 2;
                float b0 = sBias[cp], b1 = sBias[cp + 1];
                int hh8 = (cp >> 4) & 7, e = cp & 15;
                #pragma unroll
                for (int rr = 0; rr < 2; ++rr) {
                    int r = m0 + wm + i * 16 + (lane >> 2) + rr * 8;
                    float v0 = (acc[i][j][rr * 2 + 0] + b0) * scale;
                    float v1 = (acc[i][j][rr * 2 + 1] + b1) * scale;
                    int bb = r >> 10, t = r & 1023;
                    int bh128 = bb * 8 + hh8;
                    size_t idx = ((size_t)bh128 * 1024 + t) * 16 + e;
                    if (dstl) {
                        uint32_t hh, ll;
                        split2(v0, v1, hh, ll);
                        *(uint32_t*)(dsth + idx) = hh;
                        *(uint32_t*)(dstl + idx) = ll;
                    } else {
                        *(uint32_t*)(dsth + idx) = pack2(v0, v1);
                    }
                }
            }
    } else if (!(flags & FL_LN)) {
        #pragma unroll
        for (int i = 0; i < 2; ++i)
            #pragma unroll
            for (int j = 0; j < 4; ++j) {
                int cp = wn + j * 8 + (lane & 3) * 2;
                float b0 = sBias[cp], b1 = sBias[cp + 1];
                int r0 = m0 + wm + i * 16 + (lane >> 2);
                float v0 = acc[i][j][0] + b0, v1 = acc[i][j][1] + b1;
                float v2 = acc[i][j][2] + b0, v3 = acc[i][j][3] + b1;
                if (flags & FL_GELU) { v0 = gelu_f(v0); v1 = gelu_f(v1); v2 = gelu_f(v2); v3 = gelu_f(v3); }
                if (flags & FL_F32) {
                    *(float2*)(Cf + (size_t)r0 * ldc + n0 + cp)       = make_float2(v0, v1);
                    *(float2*)(Cf + (size_t)(r0 + 8) * ldc + n0 + cp) = make_float2(v2, v3);
                }
                if (flags & FL_BF) {
                    uint32_t hh, ll;
                    split2(v0, v1, hh, ll);
                    *(uint32_t*)(Cbh + (size_t)r0 * ldc + n0 + cp) = hh;
                    *(uint32_t*)(Cbl + (size_t)r0 * ldc + n0 + cp) = ll;
                    split2(v2, v3, hh, ll);
                    *(uint32_t*)(Cbh + (size_t)(r0 + 8) * ldc + n0 + cp) = hh;
                    *(uint32_t*)(Cbl + (size_t)(r0 + 8) * ldc + n0 + cp) = ll;
                }
            }
    } else {
        #pragma unroll
        for (int i = 0; i < 2; ++i)
            #pragma unroll
            for (int j = 0; j < 4; ++j) {
                int cp = wn + j * 8 + (lane & 3) * 2;
                float b0 = sBias[cp], b1 = sBias[cp + 1];
                int r0 = wm + i * 16 + (lane >> 2);
                Cs[r0 * 132 + cp]           = acc[i][j][0] + b0;
                Cs[r0 * 132 + cp + 1]       = acc[i][j][1] + b1;
                Cs[(r0 + 8) * 132 + cp]     = acc[i][j][2] + b0;
                Cs[(r0 + 8) * 132 + cp + 1] = acc[i][j][3] + b1;
            }
        __syncthreads();
        for (int rr = 0; rr < 8; ++rr) {
            int row = wid * 8 + rr;
            const float* cr = Cs + row * 132 + lane * 4;
            float2 p0 = *(const float2*)(cr);
            float2 p1 = *(const float2*)(cr + 2);
            const float4 rv = *(const float4*)(resid + (size_t)(m0 + row) * 128 + lane * 4);
            float v0 = p0.x + rv.x, v1 = p0.y + rv.y, v2 = p1.x + rv.z, v3 = p1.y + rv.w;
            float s  = v0 + v1 + v2 + v3;
            float sq2 = v0 * v0 + v1 * v1 + v2 * v2 + v3 * v3;
            #pragma unroll
            for (int off = 16; off > 0; off >>= 1) {
                s   += __shfl_xor_sync(0xffffffffu, s,   off);
                sq2 += __shfl_xor_sync(0xffffffffu, sq2, off);
            }
            float mean = s * (1.f / 128.f);
            float var  = sq2 * (1.f / 128.f) - mean * mean;
            float is   = rsqrtf(var + 1e-5f);
            int cb = lane * 4;
            float o0 = (v0 - mean) * is * sG[cb]     + sBe[cb];
            float o1 = (v1 - mean) * is * sG[cb + 1] + sBe[cb + 1];
            float o2 = (v2 - mean) * is * sG[cb + 2] + sBe[cb + 2];
            float o3 = (v3 - mean) * is * sG[cb + 3] + sBe[cb + 3];
            size_t base = (size_t)(m0 + row) * 128 + cb;
            if (flags & FL_F32)
                *(float4*)(Cf + base) = make_float4(o0, o1, o2, o3);
            if (flags & FL_BF) {
                uint32_t hh, ll;
                split2(o0, o1, hh, ll);
                *(uint32_t*)(Cbh + base) = hh; *(uint32_t*)(Cbl + base) = ll;
                split2(o2, o3, hh, ll);
                *(uint32_t*)(Cbh + base + 2) = hh; *(uint32_t*)(Cbl + base + 2) = ll;
            }
        }
    }
}

// ---------------------------------------------------------------------------
// Flash-style causal attention via HMMA, DIAGONAL-BALANCED, 8 warps/CTA,
// cp.async double-buffered staging. ex2-domain softmax (Q pre-scaled).
// K,V,P plain bf16 (random rounding washed out by softmax averaging);
// Q hi/lo for score accuracy. Bulk steps take a maskless fast path.
// ---------------------------------------------------------------------------
struct TileAcc {
    float o[2][4];
    float lsum[2];
};

__device__ __forceinline__ void qk_scores(
    const uint32_t* aqh, const uint32_t* aql, const uint32_t* kfh, float s[2][4])
{
    #pragma unroll
    for (int jj = 0; jj < 2; ++jj)
        #pragma unroll
        for (int e = 0; e < 4; ++e) s[jj][e] = 0.f;
    #pragma unroll
    for (int jj = 0; jj < 2; ++jj) {
        uint32_t kb0 = kfh[jj], kb1 = kfh[2 + jj];
        mma_bf16(s[jj], aqh, kb0, kb1);
        mma_bf16(s[jj], aql, kb0, kb1);
    }
}

__device__ __forceinline__ void attn_step_full(
    const uint32_t* aqh, const uint32_t* aql, const uint32_t* kfh,
    const uint32_t* vbh, TileAcc& T)
{
    float s[2][4];
    qk_scores(aqh, aql, kfh, s);
    uint32_t pa[4];
    #pragma unroll
    for (int jj = 0; jj < 2; ++jj) {
        float p0 = ex2f(s[jj][0]);
        float p1 = ex2f(s[jj][1]);
        float p2 = ex2f(s[jj][2]);
        float p3 = ex2f(s[jj][3]);
        T.lsum[0] += p0 + p1;
        T.lsum[1] += p2 + p3;
        pa[jj * 2 + 0] = pack2(p0, p1);
        pa[jj * 2 + 1] = pack2(p2, p3);
    }
    #pragma unroll
    for (int nt = 0; nt < 2; ++nt)
        mma_bf16(T.o[nt], pa, vbh[nt * 2], vbh[nt * 2 + 1]);
}

__device__ __forceinline__ void attn_step_masked(
    const uint32_t* aqh, const uint32_t* aql, const uint32_t* kfh,
    int kbase, int W, int r4, int c2,
    const uint32_t* vbh, TileAcc& T)
{
    float s[2][4];
    qk_scores(aqh, aql, kfh, s);
    uint32_t pa[4];
    const int t0 = W + r4, t1 = t0 + 8;
    #pragma unroll
    for (int jj = 0; jj < 2; ++jj) {
        int ub = kbase + jj * 8 + c2;
        float p0 = (ub     <= t0) ? ex2f(s[jj][0]) : 0.f;
        float p1 = (ub + 1 <= t0) ? ex2f(s[jj][1]) : 0.f;
        float p2 = (ub     <= t1) ? ex2f(s[jj][2]) : 0.f;
        float p3 = (ub + 1 <= t1) ? ex2f(s[jj][3]) : 0.f;
        T.lsum[0] += p0 + p1;
        T.lsum[1] += p2 + p3;
        pa[jj * 2 + 0] = pack2(p0, p1);
        pa[jj * 2 + 1] = pack2(p2, p3);
    }
    #pragma unroll
    for (int nt = 0; nt < 2; ++nt)
        mma_bf16(T.o[nt], pa, vbh[nt * 2], vbh[nt * 2 + 1]);
}

__global__ __launch_bounds__(256)
void attn_mma(const __nv_bfloat16* __restrict__ Qh, const __nv_bfloat16* __restrict__ Ql,
              const __nv_bfloat16* __restrict__ Kh, const __nv_bfloat16* __restrict__ Vh,
              __nv_bfloat16* __restrict__ Oh, __nv_bfloat16* __restrict__ Ol)
{
    __shared__ __align__(16) __nv_bfloat16 sKh[2][128 * 24];
    __shared__ __align__(16) __nv_bfloat16 sVh[2][128 * 24];

    const int pa_ = blockIdx.x;
    const int bh = blockIdx.y;
    const int a = pa_, bqt = 15 - pa_;
    const int tid = threadIdx.x;
    const int w = tid >> 5, lane = tid & 31;
    const int wg = w >> 2, wi = w & 3;
    const int myqt = wg ? bqt : a;
    const int W = myqt * 64 + wi * 16;
    const int r4 = lane >> 2, c2 = (lane & 3) * 2;
    const uint32_t skh0 = smem_u32(sKh[0]), skh1 = smem_u32(sKh[1]);
    const uint32_t svh0 = smem_u32(sVh[0]), svh1 = smem_u32(sVh[1]);

    const int mi = lane >> 3, li = lane & 7;
    const uint32_t vfrag_off = (uint32_t)(((li + (mi & 1) * 8) * 24 + (mi >> 1) * 8) * 2);
    const uint32_t kfrag_off = (uint32_t)(((mi & 1) * 8 + li) * 48 + (mi >> 1) * 16);

    // stage Q: hi into sKh[0], lo into sVh[0]
    if (tid < 128) {
        int qrow = (tid < 64) ? (a * 64 + tid) : (bqt * 64 + tid - 64);
        const __nv_bfloat16* srcH = Qh + ((size_t)bh * 1024 + qrow) * 16;
        const __nv_bfloat16* srcL = Ql + ((size_t)bh * 1024 + qrow) * 16;
        *(uint4*)&sKh[0][tid * 24]     = ((const uint4*)srcH)[0];
        *(uint4*)&sKh[0][tid * 24 + 8] = ((const uint4*)srcH)[1];
        *(uint4*)&sVh[0][tid * 24]     = ((const uint4*)srcL)[0];
        *(uint4*)&sVh[0][tid * 24 + 8] = ((const uint4*)srcL)[1];
    }
    __syncthreads();

    uint32_t aqh[4], aql[4];
    {
        uint32_t row = (uint32_t)(wg * 64 + wi * 16 + (mi & 1) * 8 + li);
        uint32_t boff = row * 48 + (uint32_t)(mi >> 1) * 16;
        ldsm4(skh0 + boff, aqh);
        ldsm4(svh0 + boff, aql);
    }
    __syncthreads();

    TileAcc T;
    #pragma unroll
    for (int nt = 0; nt < 2; ++nt)
        #pragma unroll
        for (int e = 0; e < 4; ++e) T.o[nt][e] = 0.f;
    T.lsum[0] = T.lsum[1] = 0.f;

    const int strow = tid >> 1, sthalf = tid & 1;
    const uint32_t stoff = (uint32_t)strow * 48 + (uint32_t)sthalf * 16;
    const size_t stg_base = ((size_t)bh * 1024 + strow) * 16 + sthalf * 8;

    const int ntiles = (bqt + 2) >> 1;
    {
        cp16(skh0 + stoff, Kh + stg_base);
        cp16(svh0 + stoff, Vh + stg_base);
        cp_commit();
    }

    for (int tile = 0; tile < ntiles; ++tile) {
        if (tile + 1 < ntiles) {
            const size_t goff = stg_base + (size_t)((tile + 1) << 7) * 16;
            const uint32_t kh = ((tile + 1) & 1) ? skh1 : skh0;
            const uint32_t vh = ((tile + 1) & 1) ? svh1 : svh0;
            cp16(kh + stoff, Kh + goff);
            cp16(vh + stoff, Vh + goff);
            cp_commit();
            cp_wait1();
        } else {
            cp_wait0();
        }
        __syncthreads();
        const int bi = tile & 1;
        const uint32_t ckh = bi ? skh1 : skh0;
        const uint32_t cvh = bi ? svh1 : svh0;
        const int u0 = tile << 7;

        if (u0 <= W + 15) {
            #pragma unroll
            for (int kk = 0; kk < 8; ++kk) {
                const int kbase = u0 + kk * 16;
                if (kbase > W + 15) break;
                uint32_t vbh[4], kfh[4];
                uint32_t tileoff = (uint32_t)(kk * 16 * 48);
                ldsm4t(cvh + vfrag_off + tileoff, vbh);
                ldsm4(ckh + kfrag_off + tileoff, kfh);
                if (kbase + 15 <= W)
                    attn_step_full(aqh, aql, kfh, vbh, T);
                else
                    attn_step_masked(aqh, aql, kfh, kbase, W, r4, c2, vbh, T);
            }
        }
        __syncthreads();
    }

    const int b = bh >> 3, h = bh & 7;
    const int bT = b << 10;
    {
        float l0 = T.lsum[0], l1 = T.lsum[1];
        l0 += __shfl_xor_sync(0xffffffffu, l0, 1);
        l0 += __shfl_xor_sync(0xffffffffu, l0, 2);
        l1 += __shfl_xor_sync(0xffffffffu, l1, 1);
        l1 += __shfl_xor_sync(0xffffffffu, l1, 2);
        float i0 = 1.f / l0, i1 = 1.f / l1;
        int row0 = bT + W + r4;
        #pragma unroll
        for (int nt = 0; nt < 2; ++nt) {
            int col = (h << 4) + nt * 8 + c2;
            uint32_t hh, ll;
            split2(T.o[nt][0] * i0, T.o[nt][1] * i0, hh, ll);
            *(uint32_t*)(Oh + (size_t)row0 * 128 + col) = hh;
            *(uint32_t*)(Ol + (size_t)row0 * 128 + col) = ll;
            split2(T.o[nt][2] * i1, T.o[nt][3] * i1, hh, ll);
            *(uint32_t*)(Oh + (size_t)(row0 + 8) * 128 + col) = hh;
            *(uint32_t*)(Ol + (size_t)(row0 + 8) * 128 + col) = ll;
        }
    }
}

// ---------------------------------------------------------------------------
extern "C" void kernel_launch(void* const* d_in, const int* in_sizes, int n_in,
                              void* d_out, int out_size)
{
    const float* x   = (const float*)d_in[0];
    const float* Wq  = (const float*)d_in[1];
    const float* bq  = (const float*)d_in[2];
    const float* Wk  = (const float*)d_in[3];
    const float* bk  = (const float*)d_in[4];
    const float* Wv  = (const float*)d_in[5];
    const float* bv  = (const float*)d_in[6];
    const float* Wp  = (const float*)d_in[7];
    const float* bp  = (const float*)d_in[8];
    const float* W1  = (const float*)d_in[9];
    const float* b1  = (const float*)d_in[10];
    const float* W2  = (const float*)d_in[11];
    const float* b2  = (const float*)d_in[12];
    const float* g1  = (const float*)d_in[13];
    const float* be1 = (const float*)d_in[14];
    const float* g2  = (const float*)d_in[15];
    const float* be2 = (const float*)d_in[16];
    float* out = (float*)d_out;

    float *p_x1, *p_bqkv;
    __nv_bfloat16 *p_xh, *p_xl, *p_qh, *p_ql, *p_kh, *p_vh;
    __nv_bfloat16 *p_ath, *p_atl, *p_x1h, *p_x1l, *p_hih, *p_hil;
    __nv_bfloat16 *p_wqh, *p_wql, *p_wph, *p_wpl, *p_w1h, *p_w1l, *p_w2h, *p_w2l;
    cudaGetSymbolAddress((void**)&p_x1,  g_x1);
    cudaGetSymbolAddress((void**)&p_bqkv, g_bqkv);
    cudaGetSymbolAddress((void**)&p_xh,  g_xh);   cudaGetSymbolAddress((void**)&p_xl,  g_xl);
    cudaGetSymbolAddress((void**)&p_qh,  g_qh);   cudaGetSymbolAddress((void**)&p_ql,  g_ql);
    cudaGetSymbolAddress((void**)&p_kh,  g_kh);
    cudaGetSymbolAddress((void**)&p_vh,  g_vh);
    cudaGetSymbolAddress((void**)&p_ath, g_ath);  cudaGetSymbolAddress((void**)&p_atl, g_atl);
    cudaGetSymbolAddress((void**)&p_x1h, g_x1h);  cudaGetSymbolAddress((void**)&p_x1l, g_x1l);
    cudaGetSymbolAddress((void**)&p_hih, g_hih);  cudaGetSymbolAddress((void**)&p_hil, g_hil);
    cudaGetSymbolAddress((void**)&p_wqh, g_wqkv_h); cudaGetSymbolAddress((void**)&p_wql, g_wqkv_l);
    cudaGetSymbolAddress((void**)&p_wph, g_wp_h);   cudaGetSymbolAddress((void**)&p_wpl, g_wp_l);
    cudaGetSymbolAddress((void**)&p_w1h, g_w1_h);   cudaGetSymbolAddress((void**)&p_w1l, g_w1_l);
    cudaGetSymbolAddress((void**)&p_w2h, g_w2_h);   cudaGetSymbolAddress((void**)&p_w2l, g_w2_l);

    cudaFuncSetAttribute(gemm_mma, cudaFuncAttributeMaxDynamicSharedMemorySize, SM_TOTAL);

    // 1. pack weights + split input activations
    pack_kernel<<<256, 256>>>(Wq, bq, Wk, bk, Wv, bv, Wp, W1, W2);
    split_x_kernel<<<BT_TOTAL * DMODEL / 4 / 256, 256>>>(x, p_xh, p_xl);
    // 2. QKV -> bf16 head-major (q hi/lo pre-scaled by 0.25*log2e; k,v single bf16)
    gemm_mma<<<dim3(256, 3), 256, SM_TOTAL>>>(p_xh, p_xl, 128, p_wqh, p_wql,
                                              p_bqkv, nullptr, nullptr, nullptr,
                                              nullptr, nullptr, nullptr, NQKV, FL_QKV);
    // 3. causal attention (diagonal-balanced) -> bf16 hi/lo
    attn_mma<<<dim3(8, 128), 256>>>(p_qh, p_ql, p_kh, p_vh, p_ath, p_atl);
    // 4. proj + bias + resid + LN1 -> fp32 x1 + bf16 hi/lo
    gemm_mma<<<dim3(256, 1), 256, SM_TOTAL>>>(p_ath, p_atl, 128, p_wph, p_wpl,
                                              bp, x, g1, be1,
                                              p_x1, p_x1h, p_x1l, DMODEL, FL_LN | FL_F32 | FL_BF);
    // 5. MLP up + GELU -> bf16 hi/lo
    gemm_mma<<<dim3(256, 4), 256, SM_TOTAL>>>(p_x1h, p_x1l, 128, p_w1h, p_w1l,
                                              b1, nullptr, nullptr, nullptr,
                                              nullptr, p_hih, p_hil, FFDIM, FL_GELU | FL_BF);
    // 6. MLP down (K=512) + bias + resid + LN2 -> out
    gemm_mma<<<dim3(256, 1), 256, SM_TOTAL>>>(p_hih, p_hil, 512, p_w2h, p_w2l,
                                              b2, p_x1, g2, be2,
                                              out, nullptr, nullptr, DMODEL, FL_LN | FL_F32);
}

// round 17
// speedup vs baseline: 1.2722x; 1.0610x over previous
#include <cuda_runtime.h>
#include <cuda_bf16.h>
#include <cstdint>
#include <math.h>

// Block_36455682408804: transformer block  B=16 T=1024 D=128 H=8 HS=16 FF=512
#define BT_TOTAL 16384
#define DMODEL   128
#define FFDIM    512
#define NQKV     384

// ---------------------------------------------------------------------------
// device-global scratch (allocation-free, graph-capturable)
// ---------------------------------------------------------------------------
__device__ float g_x1 [BT_TOTAL * DMODEL];                // fp32 residual for MLP2
__device__ float g_bqkv[NQKV];
__device__ __nv_bfloat16 g_xh [BT_TOTAL * DMODEL];                            // x as plain bf16
__device__ __nv_bfloat16 g_qh [128 * 1024 * 16];                              // [bh][t][16], pre-scaled 0.25*log2e
__device__ __nv_bfloat16 g_kh [128 * 1024 * 16];                              // [bh][t][16]
__device__ __nv_bfloat16 g_vh [128 * 1024 * 16];                              // [bh][t][16]
__device__ __nv_bfloat16 g_ath[BT_TOTAL * DMODEL], g_atl[BT_TOTAL * DMODEL];
__device__ __nv_bfloat16 g_x1h[BT_TOTAL * DMODEL], g_x1l[BT_TOTAL * DMODEL];
__device__ __nv_bfloat16 g_hih[BT_TOTAL * FFDIM],  g_hil[BT_TOTAL * FFDIM];
__device__ __nv_bfloat16 g_wqkv_h[NQKV * DMODEL];                             // plain bf16 weights for QKV
__device__ __nv_bfloat16 g_wp_h[DMODEL * DMODEL],  g_wp_l[DMODEL * DMODEL];
__device__ __nv_bfloat16 g_w1_h[FFDIM * DMODEL],   g_w1_l[FFDIM * DMODEL];
__device__ __nv_bfloat16 g_w2_h[DMODEL * FFDIM],   g_w2_l[DMODEL * FFDIM];

// ---------------------------------------------------------------------------
// helpers
// ---------------------------------------------------------------------------
__device__ __forceinline__ void split_bf(float v, __nv_bfloat16& h, __nv_bfloat16& l) {
    h = __float2bfloat16(v);
    l = __float2bfloat16(v - __bfloat162float(h));
}
__device__ __forceinline__ void split2(float x, float y, uint32_t& h, uint32_t& l) {
    asm("cvt.rn.bf16x2.f32 %0, %1, %2;" : "=r"(h) : "f"(y), "f"(x));
    float xh = __uint_as_float(h << 16);
    float yh = __uint_as_float(h & 0xffff0000u);
    float xl = x - xh, yl = y - yh;
    asm("cvt.rn.bf16x2.f32 %0, %1, %2;" : "=r"(l) : "f"(yl), "f"(xl));
}
__device__ __forceinline__ uint32_t pack2(float x, float y) {
    uint32_t r;
    asm("cvt.rn.bf16x2.f32 %0, %1, %2;" : "=r"(r) : "f"(y), "f"(x));
    return r;
}
__device__ __forceinline__ float ex2f(float x) {
    float r; asm("ex2.approx.f32 %0, %1;" : "=f"(r) : "f"(x)); return r;
}
__device__ __forceinline__ uint32_t smem_u32(const void* p) {
    uint32_t a;
    asm("{ .reg .u64 t; cvta.to.shared.u64 t, %1; cvt.u32.u64 %0, t; }" : "=r"(a) : "l"(p));
    return a;
}
__device__ __forceinline__ void ldsm4(uint32_t addr, uint32_t* r) {
    asm volatile("ldmatrix.sync.aligned.m8n8.x4.shared.b16 {%0,%1,%2,%3}, [%4];"
                 : "=r"(r[0]), "=r"(r[1]), "=r"(r[2]), "=r"(r[3]) : "r"(addr));
}
__device__ __forceinline__ void ldsm4t(uint32_t addr, uint32_t* r) {
    asm volatile("ldmatrix.sync.aligned.m8n8.x4.trans.shared.b16 {%0,%1,%2,%3}, [%4];"
                 : "=r"(r[0]), "=r"(r[1]), "=r"(r[2]), "=r"(r[3]) : "r"(addr));
}
__device__ __forceinline__ void mma_bf16(float* d, const uint32_t* a, uint32_t b0, uint32_t b1) {
    asm volatile("mma.sync.aligned.m16n8k16.row.col.f32.bf16.bf16.f32 "
                 "{%0,%1,%2,%3}, {%4,%5,%6,%7}, {%8,%9}, {%0,%1,%2,%3};"
                 : "+f"(d[0]), "+f"(d[1]), "+f"(d[2]), "+f"(d[3])
                 : "r"(a[0]), "r"(a[1]), "r"(a[2]), "r"(a[3]), "r"(b0), "r"(b1));
}
__device__ __forceinline__ void cp16(uint32_t saddr, const void* gptr) {
    asm volatile("cp.async.cg.shared.global [%0], [%1], 16;" :: "r"(saddr), "l"(gptr));
}
__device__ __forceinline__ void cp_commit() { asm volatile("cp.async.commit_group;"); }
__device__ __forceinline__ void cp_wait0() { asm volatile("cp.async.wait_group 0;"); }
__device__ __forceinline__ void cp_wait1() { asm volatile("cp.async.wait_group 1;"); }
__device__ __forceinline__ float gelu_f(float v) {
    return 0.5f * v * (1.f + erff(v * 0.7071067811865475f));
}

// ---------------------------------------------------------------------------
// pack weights: transpose to [N,K]; qkv plain bf16, others split hi/lo
// ---------------------------------------------------------------------------
__global__ void pack_kernel(const float* __restrict__ Wq, const float* __restrict__ bq,
                            const float* __restrict__ Wk, const float* __restrict__ bk,
                            const float* __restrict__ Wv, const float* __restrict__ bv,
                            const float* __restrict__ Wp, const float* __restrict__ W1,
                            const float* __restrict__ W2)
{
    int i0 = blockIdx.x * blockDim.x + threadIdx.x;
    int stride = gridDim.x * blockDim.x;
    for (int i = i0; i < NQKV * DMODEL; i += stride) {
        int n = i >> 7, k = i & 127;
        float v;
        if (n < 128)      v = Wq[((n >> 4) << 11) + k * 16 + (n & 15)];
        else if (n < 256) { int m = n - 128; v = Wk[((m >> 4) << 11) + k * 16 + (m & 15)]; }
        else              { int m = n - 256; v = Wv[((m >> 4) << 11) + k * 16 + (m & 15)]; }
        g_wqkv_h[i] = __float2bfloat16(v);
    }
    for (int i = i0; i < DMODEL * DMODEL; i += stride) {
        int n = i >> 7, k = i & 127;
        split_bf(Wp[k * 128 + n], g_wp_h[i], g_wp_l[i]);
    }
    for (int i = i0; i < FFDIM * DMODEL; i += stride) {
        int n = i >> 7, k = i & 127;
        split_bf(W1[k * 512 + n], g_w1_h[i], g_w1_l[i]);
    }
    for (int i = i0; i < DMODEL * FFDIM; i += stride) {
        int n = i >> 9, k = i & 511;
        split_bf(W2[k * 128 + n], g_w2_h[i], g_w2_l[i]);
    }
    for (int i = i0; i < NQKV; i += stride)
        g_bqkv[i] = (i < 128) ? bq[i] : (i < 256 ? bk[i - 128] : bv[i - 256]);
}

// convert activations x -> plain bf16
__global__ void split_x_kernel(const float* __restrict__ X, __nv_bfloat16* __restrict__ Xh)
{
    int i = blockIdx.x * blockDim.x + threadIdx.x;
    float4 v = ((const float4*)X)[i];
    ((uint2*)Xh)[i] = make_uint2(pack2(v.x, v.y), pack2(v.z, v.w));
}

// ---------------------------------------------------------------------------
// HMMA GEMM, bf16 inputs, cp.async 2-stage pipeline, 256 threads.
// CTA tile 64x128 (M x N), 8 warps (2m x 4n), warp tile 32x32, K chunk 64.
// flags: 1=gelu 2=LN(+resid) 4=write fp32 8=write bf16 hi/lo 16=QKV 32=plain bf16
// ---------------------------------------------------------------------------
#define FL_GELU  1
#define FL_LN    2
#define FL_F32   4
#define FL_BF    8
#define FL_QKV   16
#define FL_PLAIN 32

#define SM_AH 0
#define SM_AL 8192
#define SM_BH 16384
#define SM_BL 32768
#define SM_STAGE 49152
#define SM_CS 0
#define SM_BIAS 98304
#define SM_G    98816
#define SM_BE   99328
#define SM_TOTAL 99840

__global__ __launch_bounds__(256, 2)
void gemm_mma(const __nv_bfloat16* __restrict__ Ah_, const __nv_bfloat16* __restrict__ Al_,
              int K,
              const __nv_bfloat16* __restrict__ Bh_, const __nv_bfloat16* __restrict__ Bl_,
              const float* __restrict__ bias, const float* __restrict__ resid,
              const float* __restrict__ gamma, const float* __restrict__ beta,
              float* __restrict__ Cf, __nv_bfloat16* __restrict__ Cbh, __nv_bfloat16* __restrict__ Cbl,
              int ldc, int flags)
{
    extern __shared__ unsigned char smraw[];
    const uint32_t smem_base = smem_u32(smraw);
    float* sBias = (float*)(smraw + SM_BIAS);
    float* sG    = (float*)(smraw + SM_G);
    float* sBe   = (float*)(smraw + SM_BE);
    float* Cs    = (float*)(smraw + SM_CS);

    const int tid = threadIdx.x;
    const int wid = tid >> 5, lane = tid & 31;
    const int m0 = blockIdx.x * 64, n0 = blockIdx.y * 128;
    const int wm = (wid & 1) * 32, wn = (wid >> 1) * 32;
    const bool plain = (flags & FL_PLAIN) != 0;

    if (tid < 128) {
        sBias[tid] = bias[n0 + tid];
        if (flags & FL_LN) { sG[tid] = gamma[tid]; sBe[tid] = beta[tid]; }
    }

    const int q = lane >> 3, rin = lane & 7;
    const int rowA0 = wm + (q & 1) * 8 + rin;
    const int kqoff = (q >> 1) * 16;

    const int ar = tid >> 2, aq = tid & 3;
    const int br = tid >> 1, bq2 = tid & 1;
    const uint32_t aswz = (uint32_t)(ar & 7) << 4;
    const uint32_t bswz = (uint32_t)(br & 7) << 4;

    float acc[2][4][4];
    #pragma unroll
    for (int i = 0; i < 2; ++i)
        #pragma unroll
        for (int j = 0; j < 4; ++j)
            #pragma unroll
            for (int e = 0; e < 4; ++e) acc[i][j][e] = 0.f;

    const int nchunks = K >> 6;
    const size_t arow = (size_t)(m0 + ar) * K;
    const size_t brow = (size_t)(n0 + br) * K;

    {
        #pragma unroll
        for (int g = 0; g < 2; ++g) {
            int slot = aq * 2 + g;
            uint32_t off = (uint32_t)ar * 128 + (((uint32_t)slot * 16) ^ aswz);
            cp16(smem_base + SM_AH + off, Ah_ + arow + slot * 8);
            if (!plain) cp16(smem_base + SM_AL + off, Al_ + arow + slot * 8);
        }
        #pragma unroll
        for (int g = 0; g < 4; ++g) {
            int slot = bq2 * 4 + g;
            uint32_t off = (uint32_t)br * 128 + (((uint32_t)slot * 16) ^ bswz);
            cp16(smem_base + SM_BH + off, Bh_ + brow + slot * 8);
            if (!plain) cp16(smem_base + SM_BL + off, Bl_ + brow + slot * 8);
        }
        cp_commit();
    }

    for (int c = 0; c < nchunks; ++c) {
        if (c + 1 < nchunks) {
            const int kc = (c + 1) << 6;
            const uint32_t sb = smem_base + ((c + 1) & 1) * SM_STAGE;
            #pragma unroll
            for (int g = 0; g < 2; ++g) {
                int slot = aq * 2 + g;
                uint32_t off = (uint32_t)ar * 128 + (((uint32_t)slot * 16) ^ aswz);
                cp16(sb + SM_AH + off, Ah_ + arow + kc + slot * 8);
                if (!plain) cp16(sb + SM_AL + off, Al_ + arow + kc + slot * 8);
            }
            #pragma unroll
            for (int g = 0; g < 4; ++g) {
                int slot = bq2 * 4 + g;
                uint32_t off = (uint32_t)br * 128 + (((uint32_t)slot * 16) ^ bswz);
                cp16(sb + SM_BH + off, Bh_ + brow + kc + slot * 8);
                if (!plain) cp16(sb + SM_BL + off, Bl_ + brow + kc + slot * 8);
            }
            cp_commit();
            cp_wait1();
        } else {
            cp_wait0();
        }
        __syncthreads();
        const uint32_t sb = smem_base + (c & 1) * SM_STAGE;
        #pragma unroll
        for (int ks = 0; ks < 4; ++ks) {
            const uint32_t kb = (uint32_t)(ks * 32 + kqoff);
            uint32_t ah[2][4], al[2][4], bh[4][2], bl[4][2];
            #pragma unroll
            for (int i = 0; i < 2; ++i) {
                uint32_t row = (uint32_t)(rowA0 + i * 16);
                uint32_t off = row * 128 + (kb ^ ((row & 7) << 4));
                ldsm4(sb + SM_AH + off, ah[i]);
                if (!plain) ldsm4(sb + SM_AL + off, al[i]);
            }
            #pragma unroll
            for (int j2 = 0; j2 < 2; ++j2) {
                uint32_t row = (uint32_t)(wn + j2 * 16 + (q & 1) * 8 + rin);
                uint32_t off = row * 128 + (kb ^ ((row & 7) << 4));
                uint32_t r4v[4];
                ldsm4(sb + SM_BH + off, r4v);
                bh[2*j2][0] = r4v[0]; bh[2*j2][1] = r4v[2];
                bh[2*j2+1][0] = r4v[1]; bh[2*j2+1][1] = r4v[3];
                if (!plain) {
                    ldsm4(sb + SM_BL + off, r4v);
                    bl[2*j2][0] = r4v[0]; bl[2*j2][1] = r4v[2];
                    bl[2*j2+1][0] = r4v[1]; bl[2*j2+1][1] = r4v[3];
                }
            }
            if (plain) {
                #pragma unroll
                for (int i = 0; i < 2; ++i)
                    #pragma unroll
                    for (int j = 0; j < 4; ++j)
                        mma_bf16(acc[i][j], ah[i], bh[j][0], bh[j][1]);
            } else {
                #pragma unroll
                for (int i = 0; i < 2; ++i)
                    #pragma unroll
                    for (int j = 0; j < 4; ++j) {
                        mma_bf16(acc[i][j], ah[i], bh[j][0], bh[j][1]);
                        mma_bf16(acc[i][j], ah[i], bl[j][0], bl[j][1]);
                        mma_bf16(acc[i][j], al[i], bh[j][0], bh[j][1]);
                    }
            }
        }
        __syncthreads();
    }

    if (flags & FL_QKV) {
        __nv_bfloat16* dsth;
        float scale;
        if (n0 == 0)        { dsth = g_qh; scale = 0.36067376022224085f; }  // 0.25*log2(e)
        else if (n0 == 128) { dsth = g_kh; scale = 1.f; }
        else                { dsth = g_vh; scale = 1.f; }
        #pragma unroll
        for (int i = 0; i < 2; ++i)
            #pragma unroll
            for (int j = 0; j < 4; ++j) {
                int cp = wn + j * 8 + (lane & 3) * 2;
                float b0 = sBias[cp], b1 = sBias[cp + 1];
                int hh8 = (cp >> 4) & 7, e = cp & 15;
                #pragma unroll
                for (int rr = 0; rr < 2; ++rr) {
                    int r = m0 + wm + i * 16 + (lane >> 2) + rr * 8;
                    float v0 = (acc[i][j][rr * 2 + 0] + b0) * scale;
                    float v1 = (acc[i][j][rr * 2 + 1] + b1) * scale;
                    int bb = r >> 10, t = r & 1023;
                    int bh128 = bb * 8 + hh8;
                    size_t idx = ((size_t)bh128 * 1024 + t) * 16 + e;
                    *(uint32_t*)(dsth + idx) = pack2(v0, v1);
                }
            }
    } else if (!(flags & FL_LN)) {
        #pragma unroll
        for (int i = 0; i < 2; ++i)
            #pragma unroll
            for (int j = 0; j < 4; ++j) {
                int cp = wn + j * 8 + (lane & 3) * 2;
                float b0 = sBias[cp], b1 = sBias[cp + 1];
                int r0 = m0 + wm + i * 16 + (lane >> 2);
                float v0 = acc[i][j][0] + b0, v1 = acc[i][j][1] + b1;
                float v2 = acc[i][j][2] + b0, v3 = acc[i][j][3] + b1;
                if (flags & FL_GELU) { v0 = gelu_f(v0); v1 = gelu_f(v1); v2 = gelu_f(v2); v3 = gelu_f(v3); }
                if (flags & FL_F32) {
                    *(float2*)(Cf + (size_t)r0 * ldc + n0 + cp)       = make_float2(v0, v1);
                    *(float2*)(Cf + (size_t)(r0 + 8) * ldc + n0 + cp) = make_float2(v2, v3);
                }
                if (flags & FL_BF) {
                    uint32_t hh, ll;
                    split2(v0, v1, hh, ll);
                    *(uint32_t*)(Cbh + (size_t)r0 * ldc + n0 + cp) = hh;
                    *(uint32_t*)(Cbl + (size_t)r0 * ldc + n0 + cp) = ll;
                    split2(v2, v3, hh, ll);
                    *(uint32_t*)(Cbh + (size_t)(r0 + 8) * ldc + n0 + cp) = hh;
                    *(uint32_t*)(Cbl + (size_t)(r0 + 8) * ldc + n0 + cp) = ll;
                }
            }
    } else {
        #pragma unroll
        for (int i = 0; i < 2; ++i)
            #pragma unroll
            for (int j = 0; j < 4; ++j) {
                int cp = wn + j * 8 + (lane & 3) * 2;
                float b0 = sBias[cp], b1 = sBias[cp + 1];
                int r0 = wm + i * 16 + (lane >> 2);
                Cs[r0 * 132 + cp]           = acc[i][j][0] + b0;
                Cs[r0 * 132 + cp + 1]       = acc[i][j][1] + b1;
                Cs[(r0 + 8) * 132 + cp]     = acc[i][j][2] + b0;
                Cs[(r0 + 8) * 132 + cp + 1] = acc[i][j][3] + b1;
            }
        __syncthreads();
        for (int rr = 0; rr < 8; ++rr) {
            int row = wid * 8 + rr;
            const float* cr = Cs + row * 132 + lane * 4;
            float2 p0 = *(const float2*)(cr);
            float2 p1 = *(const float2*)(cr + 2);
            const float4 rv = *(const float4*)(resid + (size_t)(m0 + row) * 128 + lane * 4);
            float v0 = p0.x + rv.x, v1 = p0.y + rv.y, v2 = p1.x + rv.z, v3 = p1.y + rv.w;
            float s  = v0 + v1 + v2 + v3;
            float sq2 = v0 * v0 + v1 * v1 + v2 * v2 + v3 * v3;
            #pragma unroll
            for (int off = 16; off > 0; off >>= 1) {
                s   += __shfl_xor_sync(0xffffffffu, s,   off);
                sq2 += __shfl_xor_sync(0xffffffffu, sq2, off);
            }
            float mean = s * (1.f / 128.f);
            float var  = sq2 * (1.f / 128.f) - mean * mean;
            float is   = rsqrtf(var + 1e-5f);
            int cb = lane * 4;
            float o0 = (v0 - mean) * is * sG[cb]     + sBe[cb];
            float o1 = (v1 - mean) * is * sG[cb + 1] + sBe[cb + 1];
            float o2 = (v2 - mean) * is * sG[cb + 2] + sBe[cb + 2];
            float o3 = (v3 - mean) * is * sG[cb + 3] + sBe[cb + 3];
            size_t base = (size_t)(m0 + row) * 128 + cb;
            if (flags & FL_F32)
                *(float4*)(Cf + base) = make_float4(o0, o1, o2, o3);
            if (flags & FL_BF) {
                uint32_t hh, ll;
                split2(o0, o1, hh, ll);
                *(uint32_t*)(Cbh + base) = hh; *(uint32_t*)(Cbl + base) = ll;
                split2(o2, o3, hh, ll);
                *(uint32_t*)(Cbh + base + 2) = hh; *(uint32_t*)(Cbl + base + 2) = ll;
            }
        }
    }
}

// ---------------------------------------------------------------------------
// Flash-style causal attention via HMMA, DIAGONAL-BALANCED, 8 warps/CTA,
// cp.async double-buffered staging. ex2-domain softmax (Q pre-scaled).
// Q,K,V,P all plain bf16 (rounding washed by softmax averaging).
// Bulk steps take a maskless fast path.
// ---------------------------------------------------------------------------
struct TileAcc {
    float o[2][4];
    float lsum[2];
};

__device__ __forceinline__ void qk_scores(
    const uint32_t* aqh, const uint32_t* kfh, float s[2][4])
{
    #pragma unroll
    for (int jj = 0; jj < 2; ++jj)
        #pragma unroll
        for (int e = 0; e < 4; ++e) s[jj][e] = 0.f;
    #pragma unroll
    for (int jj = 0; jj < 2; ++jj)
        mma_bf16(s[jj], aqh, kfh[jj], kfh[2 + jj]);
}

__device__ __forceinline__ void attn_step_full(
    const uint32_t* aqh, const uint32_t* kfh,
    const uint32_t* vbh, TileAcc& T)
{
    float s[2][4];
    qk_scores(aqh, kfh, s);
    uint32_t pa[4];
    #pragma unroll
    for (int jj = 0; jj < 2; ++jj) {
        float p0 = ex2f(s[jj][0]);
        float p1 = ex2f(s[jj][1]);
        float p2 = ex2f(s[jj][2]);
        float p3 = ex2f(s[jj][3]);
        T.lsum[0] += p0 + p1;
        T.lsum[1] += p2 + p3;
        pa[jj * 2 + 0] = pack2(p0, p1);
        pa[jj * 2 + 1] = pack2(p2, p3);
    }
    #pragma unroll
    for (int nt = 0; nt < 2; ++nt)
        mma_bf16(T.o[nt], pa, vbh[nt * 2], vbh[nt * 2 + 1]);
}

__device__ __forceinline__ void attn_step_masked(
    const uint32_t* aqh, const uint32_t* kfh,
    int kbase, int W, int r4, int c2,
    const uint32_t* vbh, TileAcc& T)
{
    float s[2][4];
    qk_scores(aqh, kfh, s);
    uint32_t pa[4];
    const int t0 = W + r4, t1 = t0 + 8;
    #pragma unroll
    for (int jj = 0; jj < 2; ++jj) {
        int ub = kbase + jj * 8 + c2;
        float p0 = (ub     <= t0) ? ex2f(s[jj][0]) : 0.f;
        float p1 = (ub + 1 <= t0) ? ex2f(s[jj][1]) : 0.f;
        float p2 = (ub     <= t1) ? ex2f(s[jj][2]) : 0.f;
        float p3 = (ub + 1 <= t1) ? ex2f(s[jj][3]) : 0.f;
        T.lsum[0] += p0 + p1;
        T.lsum[1] += p2 + p3;
        pa[jj * 2 + 0] = pack2(p0, p1);
        pa[jj * 2 + 1] = pack2(p2, p3);
    }
    #pragma unroll
    for (int nt = 0; nt < 2; ++nt)
        mma_bf16(T.o[nt], pa, vbh[nt * 2], vbh[nt * 2 + 1]);
}

__global__ __launch_bounds__(256)
void attn_mma(const __nv_bfloat16* __restrict__ Qh,
              const __nv_bfloat16* __restrict__ Kh, const __nv_bfloat16* __restrict__ Vh,
              __nv_bfloat16* __restrict__ Oh, __nv_bfloat16* __restrict__ Ol)
{
    __shared__ __align__(16) __nv_bfloat16 sKh[2][128 * 24];
    __shared__ __align__(16) __nv_bfloat16 sVh[2][128 * 24];

    const int pa_ = blockIdx.x;
    const int bh = blockIdx.y;
    const int a = pa_, bqt = 15 - pa_;
    const int tid = threadIdx.x;
    const int w = tid >> 5, lane = tid & 31;
    const int wg = w >> 2, wi = w & 3;
    const int myqt = wg ? bqt : a;
    const int W = myqt * 64 + wi * 16;
    const int r4 = lane >> 2, c2 = (lane & 3) * 2;
    const uint32_t skh0 = smem_u32(sKh[0]), skh1 = smem_u32(sKh[1]);
    const uint32_t svh0 = smem_u32(sVh[0]), svh1 = smem_u32(sVh[1]);

    const int mi = lane >> 3, li = lane & 7;
    const uint32_t vfrag_off = (uint32_t)(((li + (mi & 1) * 8) * 24 + (mi >> 1) * 8) * 2);
    const uint32_t kfrag_off = (uint32_t)(((mi & 1) * 8 + li) * 48 + (mi >> 1) * 16);

    // stage Q into sKh[0]
    if (tid < 128) {
        int qrow = (tid < 64) ? (a * 64 + tid) : (bqt * 64 + tid - 64);
        const __nv_bfloat16* srcH = Qh + ((size_t)bh * 1024 + qrow) * 16;
        *(uint4*)&sKh[0][tid * 24]     = ((const uint4*)srcH)[0];
        *(uint4*)&sKh[0][tid * 24 + 8] = ((const uint4*)srcH)[1];
    }
    __syncthreads();

    uint32_t aqh[4];
    {
        uint32_t row = (uint32_t)(wg * 64 + wi * 16 + (mi & 1) * 8 + li);
        uint32_t boff = row * 48 + (uint32_t)(mi >> 1) * 16;
        ldsm4(skh0 + boff, aqh);
    }
    __syncthreads();

    TileAcc T;
    #pragma unroll
    for (int nt = 0; nt < 2; ++nt)
        #pragma unroll
        for (int e = 0; e < 4; ++e) T.o[nt][e] = 0.f;
    T.lsum[0] = T.lsum[1] = 0.f;

    const int strow = tid >> 1, sthalf = tid & 1;
    const uint32_t stoff = (uint32_t)strow * 48 + (uint32_t)sthalf * 16;
    const size_t stg_base = ((size_t)bh * 1024 + strow) * 16 + sthalf * 8;

    const int ntiles = (bqt + 2) >> 1;
    {
        cp16(skh0 + stoff, Kh + stg_base);
        cp16(svh0 + stoff, Vh + stg_base);
        cp_commit();
    }

    for (int tile = 0; tile < ntiles; ++tile) {
        if (tile + 1 < ntiles) {
            const size_t goff = stg_base + (size_t)((tile + 1) << 7) * 16;
            const uint32_t kh = ((tile + 1) & 1) ? skh1 : skh0;
            const uint32_t vh = ((tile + 1) & 1) ? svh1 : svh0;
            cp16(kh + stoff, Kh + goff);
            cp16(vh + stoff, Vh + goff);
            cp_commit();
            cp_wait1();
        } else {
            cp_wait0();
        }
        __syncthreads();
        const int bi = tile & 1;
        const uint32_t ckh = bi ? skh1 : skh0;
        const uint32_t cvh = bi ? svh1 : svh0;
        const int u0 = tile << 7;

        if (u0 <= W + 15) {
            #pragma unroll
            for (int kk = 0; kk < 8; ++kk) {
                const int kbase = u0 + kk * 16;
                if (kbase > W + 15) break;
                uint32_t vbh[4], kfh[4];
                uint32_t tileoff = (uint32_t)(kk * 16 * 48);
                ldsm4t(cvh + vfrag_off + tileoff, vbh);
                ldsm4(ckh + kfrag_off + tileoff, kfh);
                if (kbase + 15 <= W)
                    attn_step_full(aqh, kfh, vbh, T);
                else
                    attn_step_masked(aqh, kfh, kbase, W, r4, c2, vbh, T);
            }
        }
        __syncthreads();
    }

    const int b = bh >> 3, h = bh & 7;
    const int bT = b << 10;
    {
        float l0 = T.lsum[0], l1 = T.lsum[1];
        l0 += __shfl_xor_sync(0xffffffffu, l0, 1);
        l0 += __shfl_xor_sync(0xffffffffu, l0, 2);
        l1 += __shfl_xor_sync(0xffffffffu, l1, 1);
        l1 += __shfl_xor_sync(0xffffffffu, l1, 2);
        float i0 = 1.f / l0, i1 = 1.f / l1;
        int row0 = bT + W + r4;
        #pragma unroll
        for (int nt = 0; nt < 2; ++nt) {
            int col = (h << 4) + nt * 8 + c2;
            uint32_t hh, ll;
            split2(T.o[nt][0] * i0, T.o[nt][1] * i0, hh, ll);
            *(uint32_t*)(Oh + (size_t)row0 * 128 + col) = hh;
            *(uint32_t*)(Ol + (size_t)row0 * 128 + col) = ll;
            split2(T.o[nt][2] * i1, T.o[nt][3] * i1, hh, ll);
            *(uint32_t*)(Oh + (size_t)(row0 + 8) * 128 + col) = hh;
            *(uint32_t*)(Ol + (size_t)(row0 + 8) * 128 + col) = ll;
        }
    }
}

// ---------------------------------------------------------------------------
extern "C" void kernel_launch(void* const* d_in, const int* in_sizes, int n_in,
                              void* d_out, int out_size)
{
    const float* x   = (const float*)d_in[0];
    const float* Wq  = (const float*)d_in[1];
    const float* bq  = (const float*)d_in[2];
    const float* Wk  = (const float*)d_in[3];
    const float* bk  = (const float*)d_in[4];
    const float* Wv  = (const float*)d_in[5];
    const float* bv  = (const float*)d_in[6];
    const float* Wp  = (const float*)d_in[7];
    const float* bp  = (const float*)d_in[8];
    const float* W1  = (const float*)d_in[9];
    const float* b1  = (const float*)d_in[10];
    const float* W2  = (const float*)d_in[11];
    const float* b2  = (const float*)d_in[12];
    const float* g1  = (const float*)d_in[13];
    const float* be1 = (const float*)d_in[14];
    const float* g2  = (const float*)d_in[15];
    const float* be2 = (const float*)d_in[16];
    float* out = (float*)d_out;

    float *p_x1, *p_bqkv;
    __nv_bfloat16 *p_xh, *p_qh, *p_kh, *p_vh;
    __nv_bfloat16 *p_ath, *p_atl, *p_x1h, *p_x1l, *p_hih, *p_hil;
    __nv_bfloat16 *p_wqh, *p_wph, *p_wpl, *p_w1h, *p_w1l, *p_w2h, *p_w2l;
    cudaGetSymbolAddress((void**)&p_x1,  g_x1);
    cudaGetSymbolAddress((void**)&p_bqkv, g_bqkv);
    cudaGetSymbolAddress((void**)&p_xh,  g_xh);
    cudaGetSymbolAddress((void**)&p_qh,  g_qh);
    cudaGetSymbolAddress((void**)&p_kh,  g_kh);
    cudaGetSymbolAddress((void**)&p_vh,  g_vh);
    cudaGetSymbolAddress((void**)&p_ath, g_ath);  cudaGetSymbolAddress((void**)&p_atl, g_atl);
    cudaGetSymbolAddress((void**)&p_x1h, g_x1h);  cudaGetSymbolAddress((void**)&p_x1l, g_x1l);
    cudaGetSymbolAddress((void**)&p_hih, g_hih);  cudaGetSymbolAddress((void**)&p_hil, g_hil);
    cudaGetSymbolAddress((void**)&p_wqh, g_wqkv_h);
    cudaGetSymbolAddress((void**)&p_wph, g_wp_h);   cudaGetSymbolAddress((void**)&p_wpl, g_wp_l);
    cudaGetSymbolAddress((void**)&p_w1h, g_w1_h);   cudaGetSymbolAddress((void**)&p_w1l, g_w1_l);
    cudaGetSymbolAddress((void**)&p_w2h, g_w2_h);   cudaGetSymbolAddress((void**)&p_w2l, g_w2_l);

    cudaFuncSetAttribute(gemm_mma, cudaFuncAttributeMaxDynamicSharedMemorySize, SM_TOTAL);

    // 1. pack weights + convert input activations
    pack_kernel<<<256, 256>>>(Wq, bq, Wk, bk, Wv, bv, Wp, W1, W2);
    split_x_kernel<<<BT_TOTAL * DMODEL / 4 / 256, 256>>>(x, p_xh);
    // 2. QKV (plain bf16) -> bf16 head-major (q pre-scaled by 0.25*log2e)
    gemm_mma<<<dim3(256, 3), 256, SM_TOTAL>>>(p_xh, nullptr, 128, p_wqh, nullptr,
                                              p_bqkv, nullptr, nullptr, nullptr,
                                              nullptr, nullptr, nullptr, NQKV, FL_QKV | FL_PLAIN);
    // 3. causal attention (diagonal-balanced) -> bf16 hi/lo
    attn_mma<<<dim3(8, 128), 256>>>(p_qh, p_kh, p_vh, p_ath, p_atl);
    // 4. proj + bias + resid + LN1 -> fp32 x1 + bf16 hi/lo
    gemm_mma<<<dim3(256, 1), 256, SM_TOTAL>>>(p_ath, p_atl, 128, p_wph, p_wpl,
                                              bp, x, g1, be1,
                                              p_x1, p_x1h, p_x1l, DMODEL, FL_LN | FL_F32 | FL_BF);
    // 5. MLP up + GELU -> bf16 hi/lo
    gemm_mma<<<dim3(256, 4), 256, SM_TOTAL>>>(p_x1h, p_x1l, 128, p_w1h, p_w1l,
                                              b1, nullptr, nullptr, nullptr,
                                              nullptr, p_hih, p_hil, FFDIM, FL_GELU | FL_BF);
    // 6. MLP down (K=512) + bias + resid + LN2 -> out
    gemm_mma<<<dim3(256, 1), 256, SM_TOTAL>>>(p_hih, p_hil, 512, p_w2h, p_w2l,
                                              b2, p_x1, g2, be2,
                                              out, nullptr, nullptr, DMODEL, FL_LN | FL_F32);
}